// round 9
// baseline (speedup 1.0000x reference)
#include <cuda_runtime.h>
#include <math.h>

#define D_MODEL 1024
#define NHEAD   16
#define DK      64
#define BATCH   2
#define SEQ     2048
#define M_TOT   (BATCH*SEQ)          // 4096
#define BHS     (BATCH*NHEAD*SEQ)    // 65536
#define OUT_E   ((size_t)M_TOT*D_MODEL)         // 4,194,304
#define ATT_E   ((size_t)BATCH*NHEAD*SEQ*SEQ)   // 134,217,728

// Scratch (static device globals — allocation APIs are forbidden).
// NOTE: these must ONLY be referenced in device code or resolved via
// cudaGetSymbolAddress. Passing the symbol directly as a kernel argument
// from host code silently uses the HOST shadow address (ATS makes it "work").
__device__ __align__(16) float g_q[OUT_E];
__device__ __align__(16) float g_k[OUT_E];
__device__ __align__(16) float g_v[OUT_E];
__device__ __align__(16) float g_ctx[OUT_E];
__device__ __align__(16) float g_attn[ATT_E];   // fallback attention buffer
__device__ float g_m[BHS];
__device__ float g_l[BHS];

// ---------------------------------------------------------------------------
// Plain GEMM: C[4096,1024] = A[4096,1024] @ W[1024,1024] + bias
// 128x128 tile, BK=8, 256 threads, 8x8 per thread.
// ---------------------------------------------------------------------------
__global__ __launch_bounds__(256)
void gemm_bias_kernel(const float* __restrict__ A, const float* __restrict__ W,
                      const float* __restrict__ bias, float* __restrict__ C)
{
    const int N = D_MODEL, K = D_MODEL;
    __shared__ float As[8][128];
    __shared__ float Ws[8][128];

    int bm = blockIdx.y * 128;
    int bn = blockIdx.x * 128;
    int tid = threadIdx.x;
    int tx = tid & 15, ty = tid >> 4;

    float acc[8][8];
#pragma unroll
    for (int i = 0; i < 8; i++)
#pragma unroll
        for (int j = 0; j < 8; j++) acc[i][j] = 0.f;

    for (int k0 = 0; k0 < K; k0 += 8) {
        {   // A tile: 128 rows x 8 k, stored transposed (scalar STS)
            int arow = tid >> 1;
            int acol = (tid & 1) << 2;
            float4 av = *(const float4*)(A + (size_t)(bm + arow) * K + k0 + acol);
            As[acol + 0][arow] = av.x;
            As[acol + 1][arow] = av.y;
            As[acol + 2][arow] = av.z;
            As[acol + 3][arow] = av.w;
        }
        {   // W tile: 8 k x 128 n (row = 512B, float4-safe)
            int wrow = tid >> 5;
            int wcol = (tid & 31) << 2;
            float4 wv = *(const float4*)(W + (size_t)(k0 + wrow) * N + bn + wcol);
            *(float4*)&Ws[wrow][wcol] = wv;
        }
        __syncthreads();
#pragma unroll
        for (int k = 0; k < 8; k++) {
            float ar[8], br[8];
#pragma unroll
            for (int i = 0; i < 8; i++) ar[i] = As[k][ty * 8 + i];
#pragma unroll
            for (int j = 0; j < 8; j++) br[j] = Ws[k][tx * 8 + j];
#pragma unroll
            for (int i = 0; i < 8; i++)
#pragma unroll
                for (int j = 0; j < 8; j++)
                    acc[i][j] = fmaf(ar[i], br[j], acc[i][j]);
        }
        __syncthreads();
    }

#pragma unroll
    for (int i = 0; i < 8; i++) {
        int m = bm + ty * 8 + i;
#pragma unroll
        for (int j = 0; j < 8; j += 4) {
            int n = bn + tx * 8 + j;
            float4 o;
            o.x = acc[i][j + 0] + bias[n + 0];
            o.y = acc[i][j + 1] + bias[n + 1];
            o.z = acc[i][j + 2] + bias[n + 2];
            o.w = acc[i][j + 3] + bias[n + 3];
            *(float4*)(C + (size_t)m * N + n) = o;
        }
    }
}

// ---------------------------------------------------------------------------
// Scores: attn[z][q][kk] = (1/8) * sum_d q[b, bm+q, h*64+d] * k[b, bn+kk, h*64+d]
// q/k in plain [B*S, D] layout. 64x64 tile, 256 threads, 4x4 per thread.
// ---------------------------------------------------------------------------
__global__ __launch_bounds__(256)
void scores_kernel(const float* __restrict__ qg, const float* __restrict__ kg,
                   float* __restrict__ attn)
{
    const float scale = 0.125f;     // 1/sqrt(64)
    int z  = blockIdx.z;            // b*NHEAD + h
    int b  = z >> 4, h = z & 15;
    int bm = blockIdx.y * 64;
    int bn = blockIdx.x * 64;
    int tid = threadIdx.x;

    __shared__ float Qs[64][65];
    __shared__ float Ks[64][65];

    const float* qb = qg + (size_t)b * SEQ * D_MODEL + h * DK;
    const float* kb = kg + (size_t)b * SEQ * D_MODEL + h * DK;

#pragma unroll
    for (int it = 0; it < 4; ++it) {
        int f = tid + it * 256;
        int r = f >> 4;
        int c = (f & 15) << 2;
        float4 qv = *(const float4*)(qb + (size_t)(bm + r) * D_MODEL + c);
        Qs[r][c + 0] = qv.x; Qs[r][c + 1] = qv.y;
        Qs[r][c + 2] = qv.z; Qs[r][c + 3] = qv.w;
        float4 kv = *(const float4*)(kb + (size_t)(bn + r) * D_MODEL + c);
        Ks[r][c + 0] = kv.x; Ks[r][c + 1] = kv.y;
        Ks[r][c + 2] = kv.z; Ks[r][c + 3] = kv.w;
    }
    __syncthreads();

    int tx = tid & 15, ty = tid >> 4;
    float acc[4][4];
#pragma unroll
    for (int i = 0; i < 4; i++)
#pragma unroll
        for (int j = 0; j < 4; j++) acc[i][j] = 0.f;

#pragma unroll
    for (int k = 0; k < 64; k++) {
        float ar[4], br[4];
#pragma unroll
        for (int i = 0; i < 4; i++) ar[i] = Qs[ty * 4 + i][k];
#pragma unroll
        for (int j = 0; j < 4; j++) br[j] = Ks[tx * 4 + j][k];
#pragma unroll
        for (int i = 0; i < 4; i++)
#pragma unroll
            for (int j = 0; j < 4; j++)
                acc[i][j] = fmaf(ar[i], br[j], acc[i][j]);
    }

    float* ab = attn + (size_t)z * SEQ * SEQ;
#pragma unroll
    for (int i = 0; i < 4; i++) {
        int r = bm + ty * 4 + i;
        float4 o;
        o.x = acc[i][0] * scale;
        o.y = acc[i][1] * scale;
        o.z = acc[i][2] * scale;
        o.w = acc[i][3] * scale;
        *(float4*)(ab + (size_t)r * SEQ + bn + tx * 4) = o;
    }
}

// ---------------------------------------------------------------------------
// Softmax stats per attention row: max and sum(exp(x-max)).
// One 128-thread block per row; row held in registers.
// ---------------------------------------------------------------------------
__global__ __launch_bounds__(128)
void softmax_stats_kernel(const float* __restrict__ attn)
{
    int row = blockIdx.x;
    const float* p = attn + (size_t)row * SEQ;
    int tid = threadIdx.x;

    float vals[16];
    float mx = -1e30f;
#pragma unroll
    for (int i = 0; i < 16; i++) {
        vals[i] = p[tid + i * 128];
        mx = fmaxf(mx, vals[i]);
    }
#pragma unroll
    for (int o = 16; o > 0; o >>= 1)
        mx = fmaxf(mx, __shfl_xor_sync(0xffffffffu, mx, o));

    __shared__ float sm[4], ss[4];
    if ((tid & 31) == 0) sm[tid >> 5] = mx;
    __syncthreads();
    mx = fmaxf(fmaxf(sm[0], sm[1]), fmaxf(sm[2], sm[3]));

    float sum = 0.f;
#pragma unroll
    for (int i = 0; i < 16; i++) sum += __expf(vals[i] - mx);
#pragma unroll
    for (int o = 16; o > 0; o >>= 1)
        sum += __shfl_xor_sync(0xffffffffu, sum, o);
    if ((tid & 31) == 0) ss[tid >> 5] = sum;
    __syncthreads();
    if (tid == 0) {
        g_m[row] = mx;
        g_l[row] = ss[0] + ss[1] + ss[2] + ss[3];
    }
}

// ---------------------------------------------------------------------------
// Context: normalize attn in-place (p = exp(s-m)/l) and accumulate ctx = P @ V.
// V in plain [B*S, D] layout (cols h*64..h*64+63). ctx written plain [B*S, D].
// ---------------------------------------------------------------------------
__global__ __launch_bounds__(256)
void context_kernel(float* __restrict__ attn, const float* __restrict__ vg,
                    float* __restrict__ ctx)
{
    int z  = blockIdx.y;           // b*NHEAD + h
    int bm = blockIdx.x * 64;
    int b = z >> 4, h = z & 15;
    int tid = threadIdx.x;

    __shared__ float Ps[64][65];
    __shared__ float Vs[64][65];
    __shared__ float mrow[64], rlrow[64];

    if (tid < 64) {
        mrow[tid]  = g_m[(size_t)z * SEQ + bm + tid];
        rlrow[tid] = 1.0f / g_l[(size_t)z * SEQ + bm + tid];
    }
    __syncthreads();

    float* ab = attn + (size_t)z * SEQ * SEQ;
    const float* vb = vg + (size_t)b * SEQ * D_MODEL + h * DK;
    int tx = tid & 15, ty = tid >> 4;

    float acc[4][4];
#pragma unroll
    for (int i = 0; i < 4; i++)
#pragma unroll
        for (int j = 0; j < 4; j++) acc[i][j] = 0.f;

    for (int k0 = 0; k0 < SEQ; k0 += 64) {
#pragma unroll
        for (int it = 0; it < 4; ++it) {
            int f = tid + it * 256;
            int r = f >> 4;
            int c = (f & 15) << 2;
            float* gp = ab + (size_t)(bm + r) * SEQ + k0 + c;
            float4 sv = *(float4*)gp;
            float m = mrow[r], rl = rlrow[r];
            sv.x = __expf(sv.x - m) * rl;
            sv.y = __expf(sv.y - m) * rl;
            sv.z = __expf(sv.z - m) * rl;
            sv.w = __expf(sv.w - m) * rl;
            *(float4*)gp = sv;            // final normalized attention
            Ps[r][c + 0] = sv.x; Ps[r][c + 1] = sv.y;
            Ps[r][c + 2] = sv.z; Ps[r][c + 3] = sv.w;
            float4 vv = *(const float4*)(vb + (size_t)(k0 + r) * D_MODEL + c);
            Vs[r][c + 0] = vv.x; Vs[r][c + 1] = vv.y;
            Vs[r][c + 2] = vv.z; Vs[r][c + 3] = vv.w;
        }
        __syncthreads();
#pragma unroll
        for (int k = 0; k < 64; k++) {
            float ar[4], br[4];
#pragma unroll
            for (int i = 0; i < 4; i++) ar[i] = Ps[ty * 4 + i][k];
#pragma unroll
            for (int j = 0; j < 4; j++) br[j] = Vs[k][tx * 4 + j];
#pragma unroll
            for (int i = 0; i < 4; i++)
#pragma unroll
                for (int j = 0; j < 4; j++)
                    acc[i][j] = fmaf(ar[i], br[j], acc[i][j]);
        }
        __syncthreads();
    }

#pragma unroll
    for (int i = 0; i < 4; i++) {
        int srow = bm + ty * 4 + i;
        float4 o;
        o.x = acc[i][0]; o.y = acc[i][1]; o.z = acc[i][2]; o.w = acc[i][3];
        *(float4*)(ctx + ((size_t)(b * SEQ + srow)) * D_MODEL + h * DK + tx * 4) = o;
    }
}

// ---------------------------------------------------------------------------
extern "C" void kernel_launch(void* const* d_in, const int* in_sizes, int n_in,
                              void* d_out, int out_size)
{
    const float* Q   = (const float*)d_in[0];
    const float* K   = (const float*)d_in[1];
    const float* V   = (const float*)d_in[2];
    const float* Wq  = (const float*)d_in[3];
    const float* bq  = (const float*)d_in[4];
    const float* Wk  = (const float*)d_in[5];
    const float* bk  = (const float*)d_in[6];
    const float* Wv  = (const float*)d_in[7];
    const float* bv  = (const float*)d_in[8];
    const float* Wfc = (const float*)d_in[9];
    const float* bfc = (const float*)d_in[10];

    float* out = (float*)d_out;    // output 0: [B, S, D] at offset 0

    // Resolve REAL device addresses of the scratch globals. (Passing the
    // symbols directly from host code passes the host shadow address, which
    // GB300's ATS happily dereferences into host memory — silent corruption.)
    void *pq, *pk, *pv, *pc, *pa;
    cudaGetSymbolAddress(&pq, g_q);
    cudaGetSymbolAddress(&pk, g_k);
    cudaGetSymbolAddress(&pv, g_v);
    cudaGetSymbolAddress(&pc, g_ctx);
    cudaGetSymbolAddress(&pa, g_attn);
    float* dq   = (float*)pq;
    float* dk   = (float*)pk;
    float* dv   = (float*)pv;
    float* dctx = (float*)pc;

    // Output 1 (attention [B,H,S,S]) goes into d_out if it fits, else scratch.
    float* attn = ((size_t)out_size >= OUT_E + ATT_E) ? (out + OUT_E)
                                                      : (float*)pa;

    dim3 gemm_grid(D_MODEL / 128, M_TOT / 128);        // (8, 32)
    gemm_bias_kernel<<<gemm_grid, 256>>>(Q, Wq, bq, dq);
    gemm_bias_kernel<<<gemm_grid, 256>>>(K, Wk, bk, dk);
    gemm_bias_kernel<<<gemm_grid, 256>>>(V, Wv, bv, dv);

    dim3 sc_grid(SEQ / 64, SEQ / 64, BATCH * NHEAD);   // (32, 32, 32)
    scores_kernel<<<sc_grid, 256>>>(dq, dk, attn);

    softmax_stats_kernel<<<BHS, 128>>>(attn);

    dim3 ctx_grid(SEQ / 64, BATCH * NHEAD);            // (32, 32)
    context_kernel<<<ctx_grid, 256>>>(attn, dv, dctx);

    gemm_bias_kernel<<<gemm_grid, 256>>>(dctx, Wfc, bfc, out);
}

// round 10
// speedup vs baseline: 1.3225x; 1.3225x over previous
#include <cuda_runtime.h>
#include <cuda_bf16.h>
#include <math.h>
#include <stdint.h>

#define D_MODEL 1024
#define NHEAD   16
#define DK      64
#define BATCH   2
#define SEQ     2048
#define M_TOT   (BATCH*SEQ)          // 4096
#define BHS     (BATCH*NHEAD*SEQ)    // 65536
#define OUT_E   ((size_t)M_TOT*D_MODEL)         // 4,194,304
#define ATT_E   ((size_t)BATCH*NHEAD*SEQ*SEQ)   // 134,217,728

// Scratch (static device globals). Only ever dereferenced in device code or
// resolved with cudaGetSymbolAddress (host shadow address trap on GB300/ATS).
__device__ __align__(16) float g_q[OUT_E];
__device__ __align__(16) float g_k[OUT_E];
__device__ __align__(16) float g_v[OUT_E];
__device__ __align__(16) float g_ctx[OUT_E];
__device__ __align__(16) float g_attn[ATT_E];
__device__ float g_m[BHS];
__device__ float g_l[BHS];

static __device__ __forceinline__ uint32_t smem_u32(const void* p) {
    return (uint32_t)__cvta_generic_to_shared(p);
}

// Split fp32 -> (hi: truncated bf16, lo: bf16(x - hi)). |lo| <= 2^-8 |x|,
// residual after using both terms ~2^-17 |x|.
static __device__ __forceinline__ void split_bf16(float x, __nv_bfloat16& hi, __nv_bfloat16& lo) {
    uint32_t u = __float_as_uint(x) & 0xFFFF0000u;
    hi = __ushort_as_bfloat16((unsigned short)(u >> 16));
    lo = __float2bfloat16(x - __uint_as_float(u));
}

#define MMA_BF16(Cr, Ar, B0, B1)                                               \
    asm volatile(                                                              \
        "mma.sync.aligned.m16n8k16.row.col.f32.bf16.bf16.f32 "                 \
        "{%0,%1,%2,%3},{%4,%5,%6,%7},{%8,%9},{%0,%1,%2,%3};"                   \
        : "+f"(Cr[0]), "+f"(Cr[1]), "+f"(Cr[2]), "+f"(Cr[3])                   \
        : "r"(Ar[0]), "r"(Ar[1]), "r"(Ar[2]), "r"(Ar[3]), "r"(B0), "r"(B1))

#define LDMATRIX_X4(R, addr)                                                   \
    asm volatile("ldmatrix.sync.aligned.m8n8.x4.shared.b16 {%0,%1,%2,%3}, [%4];" \
        : "=r"(R[0]), "=r"(R[1]), "=r"(R[2]), "=r"(R[3]) : "r"(addr))

#define LDMATRIX_X2_T(R, addr)                                                 \
    asm volatile("ldmatrix.sync.aligned.m8n8.x2.trans.shared.b16 {%0,%1}, [%2];" \
        : "=r"(R[0]), "=r"(R[1]) : "r"(addr))

// ---------------------------------------------------------------------------
// Split-bf16 tensor-core GEMM: C[4096,1024] = A @ W + bias   (fp32 in/out)
// BM=BN=128, BK=32, 256 threads (8 warps, 2x4), warp tile 64x32,
// per warp 4x4 m16n8 tiles, 3 mmas per tile per k16 (hi*hi + hi*lo + lo*hi).
// fp32 operands converted to split-bf16 during the smem staging store.
// ---------------------------------------------------------------------------
__global__ __launch_bounds__(256)
void gemm_bias_mma(const float* __restrict__ A, const float* __restrict__ W,
                   const float* __restrict__ bias, float* __restrict__ C)
{
    const int LDA = 40;   // 32 + 8 pad (bf16 elems); row = 80B (16B-aligned)
    const int LDB = 136;  // 128 + 8 pad;            row = 272B (16B-aligned)
    __shared__ __nv_bfloat16 Ah[128 * LDA], Al[128 * LDA];
    __shared__ __nv_bfloat16 Bh[32 * LDB],  Bl[32 * LDB];

    int tid  = threadIdx.x;
    int lane = tid & 31, warp = tid >> 5;
    int bm = blockIdx.y * 128, bn = blockIdx.x * 128;
    int wm = (warp & 1) * 64, wn = (warp >> 1) * 32;

    float c[4][4][4];
#pragma unroll
    for (int mt = 0; mt < 4; mt++)
#pragma unroll
        for (int nt = 0; nt < 4; nt++)
#pragma unroll
            for (int e = 0; e < 4; e++) c[mt][nt][e] = 0.f;

    for (int k0 = 0; k0 < D_MODEL; k0 += 32) {
        // --- Stage A tile (128 x 32 fp32 -> split bf16). 1024 float4, 4/thread.
#pragma unroll
        for (int i = 0; i < 4; i++) {
            int idx = tid + i * 256;
            int row = idx >> 3;            // 0..127
            int col = (idx & 7) << 2;      // 0..28
            float4 v = *(const float4*)(A + (size_t)(bm + row) * D_MODEL + k0 + col);
            __nv_bfloat16 h0,h1,h2,h3,l0,l1,l2,l3;
            split_bf16(v.x, h0, l0); split_bf16(v.y, h1, l1);
            split_bf16(v.z, h2, l2); split_bf16(v.w, h3, l3);
            __nv_bfloat162* dh = (__nv_bfloat162*)&Ah[row * LDA + col];
            __nv_bfloat162* dl = (__nv_bfloat162*)&Al[row * LDA + col];
            dh[0] = __nv_bfloat162(h0, h1); dh[1] = __nv_bfloat162(h2, h3);
            dl[0] = __nv_bfloat162(l0, l1); dl[1] = __nv_bfloat162(l2, l3);
        }
        // --- Stage W tile (32 x 128 fp32 -> split bf16). 1024 float4, 4/thread.
#pragma unroll
        for (int i = 0; i < 4; i++) {
            int idx = tid + i * 256;
            int row = idx >> 5;            // 0..31
            int col = (idx & 31) << 2;     // 0..124
            float4 v = *(const float4*)(W + (size_t)(k0 + row) * D_MODEL + bn + col);
            __nv_bfloat16 h0,h1,h2,h3,l0,l1,l2,l3;
            split_bf16(v.x, h0, l0); split_bf16(v.y, h1, l1);
            split_bf16(v.z, h2, l2); split_bf16(v.w, h3, l3);
            __nv_bfloat162* dh = (__nv_bfloat162*)&Bh[row * LDB + col];
            __nv_bfloat162* dl = (__nv_bfloat162*)&Bl[row * LDB + col];
            dh[0] = __nv_bfloat162(h0, h1); dh[1] = __nv_bfloat162(h2, h3);
            dl[0] = __nv_bfloat162(l0, l1); dl[1] = __nv_bfloat162(l2, l3);
        }
        __syncthreads();

#pragma unroll
        for (int ks = 0; ks < 2; ks++) {
            int kb = ks * 16;
            // A fragments (hi & lo) for 4 m-tiles
            uint32_t ah[4][4], al[4][4];
            {
                int grp = lane >> 3, r = lane & 7;
                int arow = wm + (grp & 1) * 8 + r;
                int acol = kb + ((grp & 2) ? 8 : 0);
#pragma unroll
                for (int mt = 0; mt < 4; mt++) {
                    uint32_t a1 = smem_u32(&Ah[(arow + mt * 16) * LDA + acol]);
                    LDMATRIX_X4(ah[mt], a1);
                    uint32_t a2 = smem_u32(&Al[(arow + mt * 16) * LDA + acol]);
                    LDMATRIX_X4(al[mt], a2);
                }
            }
            // B fragments (hi & lo) for 4 n-tiles
            uint32_t bh[4][2], bl[4][2];
            {
                int r = lane & 7;
                int brow = kb + ((lane >> 3) & 1) * 8 + r;
#pragma unroll
                for (int nt = 0; nt < 4; nt++) {
                    int bcol = wn + nt * 8;
                    uint32_t a1 = smem_u32(&Bh[brow * LDB + bcol]);
                    LDMATRIX_X2_T(bh[nt], a1);
                    uint32_t a2 = smem_u32(&Bl[brow * LDB + bcol]);
                    LDMATRIX_X2_T(bl[nt], a2);
                }
            }
#pragma unroll
            for (int mt = 0; mt < 4; mt++)
#pragma unroll
                for (int nt = 0; nt < 4; nt++) {
                    MMA_BF16(c[mt][nt], ah[mt], bh[nt][0], bh[nt][1]);
                    MMA_BF16(c[mt][nt], ah[mt], bl[nt][0], bl[nt][1]);
                    MMA_BF16(c[mt][nt], al[mt], bh[nt][0], bh[nt][1]);
                }
        }
        __syncthreads();
    }

    // Epilogue: c frag (m16n8): rows lane>>2 and +8; cols (lane&3)*2, +1.
#pragma unroll
    for (int mt = 0; mt < 4; mt++) {
#pragma unroll
        for (int nt = 0; nt < 4; nt++) {
            int row0 = bm + wm + mt * 16 + (lane >> 2);
            int col  = bn + wn + nt * 8 + (lane & 3) * 2;
            float b0 = bias[col], b1 = bias[col + 1];
            float2 o0 = make_float2(c[mt][nt][0] + b0, c[mt][nt][1] + b1);
            float2 o1 = make_float2(c[mt][nt][2] + b0, c[mt][nt][3] + b1);
            *(float2*)(C + (size_t)row0 * D_MODEL + col)       = o0;
            *(float2*)(C + (size_t)(row0 + 8) * D_MODEL + col) = o1;
        }
    }
}

// ---------------------------------------------------------------------------
// Scores: attn[z][q][kk] = (1/8) * sum_d q·k ; plain [B*S, D] inputs.
// (unchanged from validated R7 kernel)
// ---------------------------------------------------------------------------
__global__ __launch_bounds__(256)
void scores_kernel(const float* __restrict__ qg, const float* __restrict__ kg,
                   float* __restrict__ attn)
{
    const float scale = 0.125f;
    int z  = blockIdx.z;
    int b  = z >> 4, h = z & 15;
    int bm = blockIdx.y * 64;
    int bn = blockIdx.x * 64;
    int tid = threadIdx.x;

    __shared__ float Qs[64][65];
    __shared__ float Ks[64][65];

    const float* qb = qg + (size_t)b * SEQ * D_MODEL + h * DK;
    const float* kb = kg + (size_t)b * SEQ * D_MODEL + h * DK;

#pragma unroll
    for (int it = 0; it < 4; ++it) {
        int f = tid + it * 256;
        int r = f >> 4;
        int c = (f & 15) << 2;
        float4 qv = *(const float4*)(qb + (size_t)(bm + r) * D_MODEL + c);
        Qs[r][c + 0] = qv.x; Qs[r][c + 1] = qv.y;
        Qs[r][c + 2] = qv.z; Qs[r][c + 3] = qv.w;
        float4 kv = *(const float4*)(kb + (size_t)(bn + r) * D_MODEL + c);
        Ks[r][c + 0] = kv.x; Ks[r][c + 1] = kv.y;
        Ks[r][c + 2] = kv.z; Ks[r][c + 3] = kv.w;
    }
    __syncthreads();

    int tx = tid & 15, ty = tid >> 4;
    float acc[4][4];
#pragma unroll
    for (int i = 0; i < 4; i++)
#pragma unroll
        for (int j = 0; j < 4; j++) acc[i][j] = 0.f;

#pragma unroll
    for (int k = 0; k < 64; k++) {
        float ar[4], br[4];
#pragma unroll
        for (int i = 0; i < 4; i++) ar[i] = Qs[ty * 4 + i][k];
#pragma unroll
        for (int j = 0; j < 4; j++) br[j] = Ks[tx * 4 + j][k];
#pragma unroll
        for (int i = 0; i < 4; i++)
#pragma unroll
            for (int j = 0; j < 4; j++)
                acc[i][j] = fmaf(ar[i], br[j], acc[i][j]);
    }

    float* ab = attn + (size_t)z * SEQ * SEQ;
#pragma unroll
    for (int i = 0; i < 4; i++) {
        int r = bm + ty * 4 + i;
        float4 o;
        o.x = acc[i][0] * scale;
        o.y = acc[i][1] * scale;
        o.z = acc[i][2] * scale;
        o.w = acc[i][3] * scale;
        *(float4*)(ab + (size_t)r * SEQ + bn + tx * 4) = o;
    }
}

// ---------------------------------------------------------------------------
__global__ __launch_bounds__(128)
void softmax_stats_kernel(const float* __restrict__ attn)
{
    int row = blockIdx.x;
    const float* p = attn + (size_t)row * SEQ;
    int tid = threadIdx.x;

    float vals[16];
    float mx = -1e30f;
#pragma unroll
    for (int i = 0; i < 16; i++) {
        vals[i] = p[tid + i * 128];
        mx = fmaxf(mx, vals[i]);
    }
#pragma unroll
    for (int o = 16; o > 0; o >>= 1)
        mx = fmaxf(mx, __shfl_xor_sync(0xffffffffu, mx, o));

    __shared__ float sm[4], ss[4];
    if ((tid & 31) == 0) sm[tid >> 5] = mx;
    __syncthreads();
    mx = fmaxf(fmaxf(sm[0], sm[1]), fmaxf(sm[2], sm[3]));

    float sum = 0.f;
#pragma unroll
    for (int i = 0; i < 16; i++) sum += __expf(vals[i] - mx);
#pragma unroll
    for (int o = 16; o > 0; o >>= 1)
        sum += __shfl_xor_sync(0xffffffffu, sum, o);
    if ((tid & 31) == 0) ss[tid >> 5] = sum;
    __syncthreads();
    if (tid == 0) {
        g_m[row] = mx;
        g_l[row] = ss[0] + ss[1] + ss[2] + ss[3];
    }
}

// ---------------------------------------------------------------------------
__global__ __launch_bounds__(256)
void context_kernel(float* __restrict__ attn, const float* __restrict__ vg,
                    float* __restrict__ ctx)
{
    int z  = blockIdx.y;
    int bm = blockIdx.x * 64;
    int b = z >> 4, h = z & 15;
    int tid = threadIdx.x;

    __shared__ float Ps[64][65];
    __shared__ float Vs[64][65];
    __shared__ float mrow[64], rlrow[64];

    if (tid < 64) {
        mrow[tid]  = g_m[(size_t)z * SEQ + bm + tid];
        rlrow[tid] = 1.0f / g_l[(size_t)z * SEQ + bm + tid];
    }
    __syncthreads();

    float* ab = attn + (size_t)z * SEQ * SEQ;
    const float* vb = vg + (size_t)b * SEQ * D_MODEL + h * DK;
    int tx = tid & 15, ty = tid >> 4;

    float acc[4][4];
#pragma unroll
    for (int i = 0; i < 4; i++)
#pragma unroll
        for (int j = 0; j < 4; j++) acc[i][j] = 0.f;

    for (int k0 = 0; k0 < SEQ; k0 += 64) {
#pragma unroll
        for (int it = 0; it < 4; ++it) {
            int f = tid + it * 256;
            int r = f >> 4;
            int c = (f & 15) << 2;
            float* gp = ab + (size_t)(bm + r) * SEQ + k0 + c;
            float4 sv = *(float4*)gp;
            float m = mrow[r], rl = rlrow[r];
            sv.x = __expf(sv.x - m) * rl;
            sv.y = __expf(sv.y - m) * rl;
            sv.z = __expf(sv.z - m) * rl;
            sv.w = __expf(sv.w - m) * rl;
            *(float4*)gp = sv;
            Ps[r][c + 0] = sv.x; Ps[r][c + 1] = sv.y;
            Ps[r][c + 2] = sv.z; Ps[r][c + 3] = sv.w;
            float4 vv = *(const float4*)(vb + (size_t)(k0 + r) * D_MODEL + c);
            Vs[r][c + 0] = vv.x; Vs[r][c + 1] = vv.y;
            Vs[r][c + 2] = vv.z; Vs[r][c + 3] = vv.w;
        }
        __syncthreads();
#pragma unroll
        for (int k = 0; k < 64; k++) {
            float ar[4], br[4];
#pragma unroll
            for (int i = 0; i < 4; i++) ar[i] = Ps[ty * 4 + i][k];
#pragma unroll
            for (int j = 0; j < 4; j++) br[j] = Vs[k][tx * 4 + j];
#pragma unroll
            for (int i = 0; i < 4; i++)
#pragma unroll
                for (int j = 0; j < 4; j++)
                    acc[i][j] = fmaf(ar[i], br[j], acc[i][j]);
        }
        __syncthreads();
    }

#pragma unroll
    for (int i = 0; i < 4; i++) {
        int srow = bm + ty * 4 + i;
        float4 o;
        o.x = acc[i][0]; o.y = acc[i][1]; o.z = acc[i][2]; o.w = acc[i][3];
        *(float4*)(ctx + ((size_t)(b * SEQ + srow)) * D_MODEL + h * DK + tx * 4) = o;
    }
}

// ---------------------------------------------------------------------------
extern "C" void kernel_launch(void* const* d_in, const int* in_sizes, int n_in,
                              void* d_out, int out_size)
{
    const float* Q   = (const float*)d_in[0];
    const float* K   = (const float*)d_in[1];
    const float* V   = (const float*)d_in[2];
    const float* Wq  = (const float*)d_in[3];
    const float* bq  = (const float*)d_in[4];
    const float* Wk  = (const float*)d_in[5];
    const float* bk  = (const float*)d_in[6];
    const float* Wv  = (const float*)d_in[7];
    const float* bv  = (const float*)d_in[8];
    const float* Wfc = (const float*)d_in[9];
    const float* bfc = (const float*)d_in[10];

    float* out = (float*)d_out;

    void *pq, *pk, *pv, *pc, *pa;
    cudaGetSymbolAddress(&pq, g_q);
    cudaGetSymbolAddress(&pk, g_k);
    cudaGetSymbolAddress(&pv, g_v);
    cudaGetSymbolAddress(&pc, g_ctx);
    cudaGetSymbolAddress(&pa, g_attn);
    float* dq   = (float*)pq;
    float* dk   = (float*)pk;
    float* dv   = (float*)pv;
    float* dctx = (float*)pc;

    float* attn = ((size_t)out_size >= OUT_E + ATT_E) ? (out + OUT_E)
                                                      : (float*)pa;

    dim3 gemm_grid(D_MODEL / 128, M_TOT / 128);        // (8, 32)
    gemm_bias_mma<<<gemm_grid, 256>>>(Q, Wq, bq, dq);
    gemm_bias_mma<<<gemm_grid, 256>>>(K, Wk, bk, dk);
    gemm_bias_mma<<<gemm_grid, 256>>>(V, Wv, bv, dv);

    dim3 sc_grid(SEQ / 64, SEQ / 64, BATCH * NHEAD);   // (32, 32, 32)
    scores_kernel<<<sc_grid, 256>>>(dq, dk, attn);

    softmax_stats_kernel<<<BHS, 128>>>(attn);

    dim3 ctx_grid(SEQ / 64, BATCH * NHEAD);            // (32, 32)
    context_kernel<<<ctx_grid, 256>>>(attn, dv, dctx);

    gemm_bias_mma<<<gemm_grid, 256>>>(dctx, Wfc, bfc, out);
}

// round 11
// speedup vs baseline: 1.9233x; 1.4543x over previous
#include <cuda_runtime.h>
#include <cuda_bf16.h>
#include <math.h>
#include <stdint.h>

#define D_MODEL 1024
#define NHEAD   16
#define DK      64
#define BATCH   2
#define SEQ     2048
#define M_TOT   (BATCH*SEQ)          // 4096
#define BHS     (BATCH*NHEAD*SEQ)    // 65536
#define OUT_E   ((size_t)M_TOT*D_MODEL)         // 4,194,304
#define ATT_E   ((size_t)BATCH*NHEAD*SEQ*SEQ)   // 134,217,728

// Scratch (static device globals). Only dereferenced in device code or
// resolved with cudaGetSymbolAddress (host-shadow/ATS trap on GB300).
__device__ __align__(16) float g_q[OUT_E];
__device__ __align__(16) float g_k[OUT_E];
__device__ __align__(16) float g_v[OUT_E];
__device__ __align__(16) float g_ctx[OUT_E];
__device__ __align__(16) float g_attn[ATT_E];
__device__ float g_m[BHS];
__device__ float g_l[BHS];

static __device__ __forceinline__ uint32_t smem_u32(const void* p) {
    return (uint32_t)__cvta_generic_to_shared(p);
}

// fp32 -> (hi: truncated bf16, lo: bf16(x-hi)); 3-term product error ~2^-17.
static __device__ __forceinline__ void split_bf16(float x, __nv_bfloat16& hi, __nv_bfloat16& lo) {
    uint32_t u = __float_as_uint(x) & 0xFFFF0000u;
    hi = __ushort_as_bfloat16((unsigned short)(u >> 16));
    lo = __float2bfloat16(x - __uint_as_float(u));
}

#define MMA_BF16(Cr, Ar, B0, B1)                                               \
    asm volatile(                                                              \
        "mma.sync.aligned.m16n8k16.row.col.f32.bf16.bf16.f32 "                 \
        "{%0,%1,%2,%3},{%4,%5,%6,%7},{%8,%9},{%0,%1,%2,%3};"                   \
        : "+f"(Cr[0]), "+f"(Cr[1]), "+f"(Cr[2]), "+f"(Cr[3])                   \
        : "r"(Ar[0]), "r"(Ar[1]), "r"(Ar[2]), "r"(Ar[3]), "r"(B0), "r"(B1))

#define LDMATRIX_X4(R, addr)                                                   \
    asm volatile("ldmatrix.sync.aligned.m8n8.x4.shared.b16 {%0,%1,%2,%3}, [%4];" \
        : "=r"(R[0]), "=r"(R[1]), "=r"(R[2]), "=r"(R[3]) : "r"(addr))

#define LDMATRIX_X2(R, addr)                                                   \
    asm volatile("ldmatrix.sync.aligned.m8n8.x2.shared.b16 {%0,%1}, [%2];"     \
        : "=r"(R[0]), "=r"(R[1]) : "r"(addr))

#define LDMATRIX_X2_T(R, addr)                                                 \
    asm volatile("ldmatrix.sync.aligned.m8n8.x2.trans.shared.b16 {%0,%1}, [%2];" \
        : "=r"(R[0]), "=r"(R[1]) : "r"(addr))

static __device__ __forceinline__ void store_split4(__nv_bfloat16* dh, __nv_bfloat16* dl, float4 v) {
    __nv_bfloat16 h0,h1,h2,h3,l0,l1,l2,l3;
    split_bf16(v.x, h0, l0); split_bf16(v.y, h1, l1);
    split_bf16(v.z, h2, l2); split_bf16(v.w, h3, l3);
    ((__nv_bfloat162*)dh)[0] = __nv_bfloat162(h0, h1);
    ((__nv_bfloat162*)dh)[1] = __nv_bfloat162(h2, h3);
    ((__nv_bfloat162*)dl)[0] = __nv_bfloat162(l0, l1);
    ((__nv_bfloat162*)dl)[1] = __nv_bfloat162(l2, l3);
}

// ---------------------------------------------------------------------------
// Split-bf16 tensor-core GEMM: C[4096,1024] = A @ W + bias   (validated R10)
// ---------------------------------------------------------------------------
__global__ __launch_bounds__(256)
void gemm_bias_mma(const float* __restrict__ A, const float* __restrict__ W,
                   const float* __restrict__ bias, float* __restrict__ C)
{
    const int LDA = 40;   // 80B rows (16B-aligned)
    const int LDB = 136;  // 272B rows (16B-aligned)
    __shared__ __nv_bfloat16 Ah[128 * LDA], Al[128 * LDA];
    __shared__ __nv_bfloat16 Bh[32 * LDB],  Bl[32 * LDB];

    int tid  = threadIdx.x;
    int lane = tid & 31, warp = tid >> 5;
    int bm = blockIdx.y * 128, bn = blockIdx.x * 128;
    int wm = (warp & 1) * 64, wn = (warp >> 1) * 32;

    float c[4][4][4];
#pragma unroll
    for (int mt = 0; mt < 4; mt++)
#pragma unroll
        for (int nt = 0; nt < 4; nt++)
#pragma unroll
            for (int e = 0; e < 4; e++) c[mt][nt][e] = 0.f;

    for (int k0 = 0; k0 < D_MODEL; k0 += 32) {
#pragma unroll
        for (int i = 0; i < 4; i++) {
            int idx = tid + i * 256;
            int row = idx >> 3, col = (idx & 7) << 2;
            float4 v = *(const float4*)(A + (size_t)(bm + row) * D_MODEL + k0 + col);
            store_split4(&Ah[row * LDA + col], &Al[row * LDA + col], v);
        }
#pragma unroll
        for (int i = 0; i < 4; i++) {
            int idx = tid + i * 256;
            int row = idx >> 5, col = (idx & 31) << 2;
            float4 v = *(const float4*)(W + (size_t)(k0 + row) * D_MODEL + bn + col);
            store_split4(&Bh[row * LDB + col], &Bl[row * LDB + col], v);
        }
        __syncthreads();

#pragma unroll
        for (int ks = 0; ks < 2; ks++) {
            int kb = ks * 16;
            uint32_t ah[4][4], al[4][4];
            {
                int grp = lane >> 3, r = lane & 7;
                int arow = wm + (grp & 1) * 8 + r;
                int acol = kb + ((grp & 2) ? 8 : 0);
#pragma unroll
                for (int mt = 0; mt < 4; mt++) {
                    LDMATRIX_X4(ah[mt], smem_u32(&Ah[(arow + mt * 16) * LDA + acol]));
                    LDMATRIX_X4(al[mt], smem_u32(&Al[(arow + mt * 16) * LDA + acol]));
                }
            }
            uint32_t bh[4][2], bl[4][2];
            {
                int brow = kb + ((lane >> 3) & 1) * 8 + (lane & 7);
#pragma unroll
                for (int nt = 0; nt < 4; nt++) {
                    int bcol = wn + nt * 8;
                    LDMATRIX_X2_T(bh[nt], smem_u32(&Bh[brow * LDB + bcol]));
                    LDMATRIX_X2_T(bl[nt], smem_u32(&Bl[brow * LDB + bcol]));
                }
            }
#pragma unroll
            for (int mt = 0; mt < 4; mt++)
#pragma unroll
                for (int nt = 0; nt < 4; nt++) {
                    MMA_BF16(c[mt][nt], ah[mt], bh[nt][0], bh[nt][1]);
                    MMA_BF16(c[mt][nt], ah[mt], bl[nt][0], bl[nt][1]);
                    MMA_BF16(c[mt][nt], al[mt], bh[nt][0], bh[nt][1]);
                }
        }
        __syncthreads();
    }

#pragma unroll
    for (int mt = 0; mt < 4; mt++)
#pragma unroll
        for (int nt = 0; nt < 4; nt++) {
            int row0 = bm + wm + mt * 16 + (lane >> 2);
            int col  = bn + wn + nt * 8 + (lane & 3) * 2;
            float b0 = bias[col], b1 = bias[col + 1];
            *(float2*)(C + (size_t)row0 * D_MODEL + col) =
                make_float2(c[mt][nt][0] + b0, c[mt][nt][1] + b1);
            *(float2*)(C + (size_t)(row0 + 8) * D_MODEL + col) =
                make_float2(c[mt][nt][2] + b0, c[mt][nt][3] + b1);
        }
}

// ---------------------------------------------------------------------------
// Scores via mma: attn[z] tile [128q x 128k] = (1/8) Q·K^T, split-bf16.
// K's natural [n][k] layout feeds the B fragment via NON-trans ldmatrix
// (k-contiguous pairs == b-frag layout). DK=64 staged once per block.
// ---------------------------------------------------------------------------
__global__ __launch_bounds__(256)
void scores_mma(const float* __restrict__ qg, const float* __restrict__ kg,
                float* __restrict__ attn)
{
    extern __shared__ __nv_bfloat16 sm_s[];
    const int LD = 72;                       // 144B rows (16B-aligned)
    __nv_bfloat16* Qh = sm_s;
    __nv_bfloat16* Ql = Qh + 128 * LD;
    __nv_bfloat16* Kh = Ql + 128 * LD;
    __nv_bfloat16* Kl = Kh + 128 * LD;

    int tid = threadIdx.x, lane = tid & 31, warp = tid >> 5;
    int z = blockIdx.z, b = z >> 4, h = z & 15;
    int bm = blockIdx.y * 128, bn = blockIdx.x * 128;
    int wm = (warp & 1) * 64, wn = (warp >> 1) * 32;

    const float* qb = qg + (size_t)b * SEQ * D_MODEL + h * DK;
    const float* kb = kg + (size_t)b * SEQ * D_MODEL + h * DK;

    // Stage Q,K tiles: 2048 float4 each, 8 per thread.
#pragma unroll
    for (int i = 0; i < 8; i++) {
        int idx = tid + i * 256;
        int row = idx >> 4, col = (idx & 15) << 2;
        float4 v = *(const float4*)(qb + (size_t)(bm + row) * D_MODEL + col);
        store_split4(&Qh[row * LD + col], &Ql[row * LD + col], v);
        float4 w = *(const float4*)(kb + (size_t)(bn + row) * D_MODEL + col);
        store_split4(&Kh[row * LD + col], &Kl[row * LD + col], w);
    }
    __syncthreads();

    float c[4][4][4];
#pragma unroll
    for (int mt = 0; mt < 4; mt++)
#pragma unroll
        for (int nt = 0; nt < 4; nt++)
#pragma unroll
            for (int e = 0; e < 4; e++) c[mt][nt][e] = 0.f;

#pragma unroll
    for (int ks = 0; ks < 4; ks++) {
        int kb16 = ks * 16;
        uint32_t ah[4][4], al[4][4];
        {
            int grp = lane >> 3, r = lane & 7;
            int arow = wm + (grp & 1) * 8 + r;
            int acol = kb16 + ((grp & 2) ? 8 : 0);
#pragma unroll
            for (int mt = 0; mt < 4; mt++) {
                LDMATRIX_X4(ah[mt], smem_u32(&Qh[(arow + mt * 16) * LD + acol]));
                LDMATRIX_X4(al[mt], smem_u32(&Ql[(arow + mt * 16) * LD + acol]));
            }
        }
        uint32_t bh[4][2], bl[4][2];
        {
            int nr = lane & 7;
            int bcol = kb16 + ((lane >> 3) & 1) * 8;
#pragma unroll
            for (int nt = 0; nt < 4; nt++) {
                int nrow = wn + nt * 8 + nr;
                LDMATRIX_X2(bh[nt], smem_u32(&Kh[nrow * LD + bcol]));
                LDMATRIX_X2(bl[nt], smem_u32(&Kl[nrow * LD + bcol]));
            }
        }
#pragma unroll
        for (int mt = 0; mt < 4; mt++)
#pragma unroll
            for (int nt = 0; nt < 4; nt++) {
                MMA_BF16(c[mt][nt], ah[mt], bh[nt][0], bh[nt][1]);
                MMA_BF16(c[mt][nt], ah[mt], bl[nt][0], bl[nt][1]);
                MMA_BF16(c[mt][nt], al[mt], bh[nt][0], bh[nt][1]);
            }
    }

    const float scale = 0.125f;
    float* ab = attn + (size_t)z * SEQ * SEQ;
#pragma unroll
    for (int mt = 0; mt < 4; mt++)
#pragma unroll
        for (int nt = 0; nt < 4; nt++) {
            int row0 = bm + wm + mt * 16 + (lane >> 2);
            int col  = bn + wn + nt * 8 + (lane & 3) * 2;
            *(float2*)(ab + (size_t)row0 * SEQ + col) =
                make_float2(c[mt][nt][0] * scale, c[mt][nt][1] * scale);
            *(float2*)(ab + (size_t)(row0 + 8) * SEQ + col) =
                make_float2(c[mt][nt][2] * scale, c[mt][nt][3] * scale);
        }
}

// ---------------------------------------------------------------------------
// Softmax stats per attention row (unchanged).
// ---------------------------------------------------------------------------
__global__ __launch_bounds__(128)
void softmax_stats_kernel(const float* __restrict__ attn)
{
    int row = blockIdx.x;
    const float* p = attn + (size_t)row * SEQ;
    int tid = threadIdx.x;

    float vals[16];
    float mx = -1e30f;
#pragma unroll
    for (int i = 0; i < 16; i++) {
        vals[i] = p[tid + i * 128];
        mx = fmaxf(mx, vals[i]);
    }
#pragma unroll
    for (int o = 16; o > 0; o >>= 1)
        mx = fmaxf(mx, __shfl_xor_sync(0xffffffffu, mx, o));

    __shared__ float sm[4], ss[4];
    if ((tid & 31) == 0) sm[tid >> 5] = mx;
    __syncthreads();
    mx = fmaxf(fmaxf(sm[0], sm[1]), fmaxf(sm[2], sm[3]));

    float sum = 0.f;
#pragma unroll
    for (int i = 0; i < 16; i++) sum += __expf(vals[i] - mx);
#pragma unroll
    for (int o = 16; o > 0; o >>= 1)
        sum += __shfl_xor_sync(0xffffffffu, sum, o);
    if ((tid & 31) == 0) ss[tid >> 5] = sum;
    __syncthreads();
    if (tid == 0) {
        g_m[row] = mx;
        g_l[row] = ss[0] + ss[1] + ss[2] + ss[3];
    }
}

// ---------------------------------------------------------------------------
// Context via mma: per (z, 128-row m-tile): loop k-chunks of 64 over SEQ.
// Normalize attn chunk (exp(s-m)/l), write back, split->smem (A operand).
// V chunk [k][n] staged hi/lo, B fragment via trans ldmatrix (GEMM-W pattern).
// ---------------------------------------------------------------------------
__global__ __launch_bounds__(256)
void context_mma(float* __restrict__ attn, const float* __restrict__ vg,
                 float* __restrict__ ctx)
{
    extern __shared__ char sm_raw[];
    const int LD = 72;
    __nv_bfloat16* Ph = (__nv_bfloat16*)sm_raw;                 // 128*LD
    __nv_bfloat16* Pl = Ph + 128 * LD;
    __nv_bfloat16* Vh = Pl + 128 * LD;                          // 64*LD
    __nv_bfloat16* Vl = Vh + 64 * LD;
    float* mrow  = (float*)(Vl + 64 * LD);                      // 128
    float* rlrow = mrow + 128;                                  // 128

    int tid = threadIdx.x, lane = tid & 31, warp = tid >> 5;
    int z = blockIdx.y, b = z >> 4, h = z & 15;
    int bm = blockIdx.x * 128;
    int wm = (warp & 1) * 64, wn = (warp >> 1) * 16;

    if (tid < 128) {
        mrow[tid]  = g_m[(size_t)z * SEQ + bm + tid];
        rlrow[tid] = 1.0f / g_l[(size_t)z * SEQ + bm + tid];
    }
    __syncthreads();

    float* ab = attn + (size_t)z * SEQ * SEQ;
    const float* vb = vg + (size_t)b * SEQ * D_MODEL + h * DK;

    float c[4][2][4];
#pragma unroll
    for (int mt = 0; mt < 4; mt++)
#pragma unroll
        for (int nt = 0; nt < 2; nt++)
#pragma unroll
            for (int e = 0; e < 4; e++) c[mt][nt][e] = 0.f;

    for (int k0 = 0; k0 < SEQ; k0 += 64) {
        // Stage P chunk: 128 x 64 fp32 = 2048 float4, 8 per thread.
#pragma unroll
        for (int i = 0; i < 8; i++) {
            int idx = tid + i * 256;
            int row = idx >> 4, col = (idx & 15) << 2;
            float* gp = ab + (size_t)(bm + row) * SEQ + k0 + col;
            float4 sv = *(float4*)gp;
            float m = mrow[row], rl = rlrow[row];
            sv.x = __expf(sv.x - m) * rl;
            sv.y = __expf(sv.y - m) * rl;
            sv.z = __expf(sv.z - m) * rl;
            sv.w = __expf(sv.w - m) * rl;
            *(float4*)gp = sv;               // final normalized attention
            store_split4(&Ph[row * LD + col], &Pl[row * LD + col], sv);
        }
        // Stage V chunk: 64 x 64 fp32 = 1024 float4, 4 per thread.
#pragma unroll
        for (int i = 0; i < 4; i++) {
            int idx = tid + i * 256;
            int row = idx >> 4, col = (idx & 15) << 2;
            float4 v = *(const float4*)(vb + (size_t)(k0 + row) * D_MODEL + col);
            store_split4(&Vh[row * LD + col], &Vl[row * LD + col], v);
        }
        __syncthreads();

#pragma unroll
        for (int ks = 0; ks < 4; ks++) {
            int kb16 = ks * 16;
            uint32_t ah[4][4], al[4][4];
            {
                int grp = lane >> 3, r = lane & 7;
                int arow = wm + (grp & 1) * 8 + r;
                int acol = kb16 + ((grp & 2) ? 8 : 0);
#pragma unroll
                for (int mt = 0; mt < 4; mt++) {
                    LDMATRIX_X4(ah[mt], smem_u32(&Ph[(arow + mt * 16) * LD + acol]));
                    LDMATRIX_X4(al[mt], smem_u32(&Pl[(arow + mt * 16) * LD + acol]));
                }
            }
            uint32_t bh[2][2], bl[2][2];
            {
                int brow = kb16 + ((lane >> 3) & 1) * 8 + (lane & 7);
#pragma unroll
                for (int nt = 0; nt < 2; nt++) {
                    int bcol = wn + nt * 8;
                    LDMATRIX_X2_T(bh[nt], smem_u32(&Vh[brow * LD + bcol]));
                    LDMATRIX_X2_T(bl[nt], smem_u32(&Vl[brow * LD + bcol]));
                }
            }
#pragma unroll
            for (int mt = 0; mt < 4; mt++)
#pragma unroll
                for (int nt = 0; nt < 2; nt++) {
                    MMA_BF16(c[mt][nt], ah[mt], bh[nt][0], bh[nt][1]);
                    MMA_BF16(c[mt][nt], ah[mt], bl[nt][0], bl[nt][1]);
                    MMA_BF16(c[mt][nt], al[mt], bh[nt][0], bh[nt][1]);
                }
        }
        __syncthreads();
    }

#pragma unroll
    for (int mt = 0; mt < 4; mt++)
#pragma unroll
        for (int nt = 0; nt < 2; nt++) {
            int row0 = bm + wm + mt * 16 + (lane >> 2);
            int col  = wn + nt * 8 + (lane & 3) * 2;
            *(float2*)(ctx + (size_t)(b * SEQ + row0) * D_MODEL + h * DK + col) =
                make_float2(c[mt][nt][0], c[mt][nt][1]);
            *(float2*)(ctx + (size_t)(b * SEQ + row0 + 8) * D_MODEL + h * DK + col) =
                make_float2(c[mt][nt][2], c[mt][nt][3]);
        }
}

// ---------------------------------------------------------------------------
extern "C" void kernel_launch(void* const* d_in, const int* in_sizes, int n_in,
                              void* d_out, int out_size)
{
    const float* Q   = (const float*)d_in[0];
    const float* K   = (const float*)d_in[1];
    const float* V   = (const float*)d_in[2];
    const float* Wq  = (const float*)d_in[3];
    const float* bq  = (const float*)d_in[4];
    const float* Wk  = (const float*)d_in[5];
    const float* bk  = (const float*)d_in[6];
    const float* Wv  = (const float*)d_in[7];
    const float* bv  = (const float*)d_in[8];
    const float* Wfc = (const float*)d_in[9];
    const float* bfc = (const float*)d_in[10];

    float* out = (float*)d_out;

    void *pq, *pk, *pv, *pc, *pa;
    cudaGetSymbolAddress(&pq, g_q);
    cudaGetSymbolAddress(&pk, g_k);
    cudaGetSymbolAddress(&pv, g_v);
    cudaGetSymbolAddress(&pc, g_ctx);
    cudaGetSymbolAddress(&pa, g_attn);
    float* dq   = (float*)pq;
    float* dk   = (float*)pk;
    float* dv   = (float*)pv;
    float* dctx = (float*)pc;

    float* attn = ((size_t)out_size >= OUT_E + ATT_E) ? (out + OUT_E)
                                                      : (float*)pa;

    const int SC_SMEM  = 4 * 128 * 72 * 2;                     // 73,728 B
    const int CTX_SMEM = (2*128*72 + 2*64*72) * 2 + 2*128*4;   // 56,320 B
    cudaFuncSetAttribute(scores_mma, cudaFuncAttributeMaxDynamicSharedMemorySize, SC_SMEM);
    cudaFuncSetAttribute(context_mma, cudaFuncAttributeMaxDynamicSharedMemorySize, CTX_SMEM);

    dim3 gemm_grid(D_MODEL / 128, M_TOT / 128);        // (8, 32)
    gemm_bias_mma<<<gemm_grid, 256>>>(Q, Wq, bq, dq);
    gemm_bias_mma<<<gemm_grid, 256>>>(K, Wk, bk, dk);
    gemm_bias_mma<<<gemm_grid, 256>>>(V, Wv, bv, dv);

    dim3 sc_grid(SEQ / 128, SEQ / 128, BATCH * NHEAD); // (16, 16, 32)
    scores_mma<<<sc_grid, 256, SC_SMEM>>>(dq, dk, attn);

    softmax_stats_kernel<<<BHS, 128>>>(attn);

    dim3 ctx_grid(SEQ / 128, BATCH * NHEAD);           // (16, 32)
    context_mma<<<ctx_grid, 256, CTX_SMEM>>>(attn, dv, dctx);

    gemm_bias_mma<<<gemm_grid, 256>>>(dctx, Wfc, bfc, out);
}

// round 14
// speedup vs baseline: 2.0861x; 1.0846x over previous
#include <cuda_runtime.h>
#include <cuda_bf16.h>
#include <math.h>
#include <stdint.h>

#define D_MODEL 1024
#define NHEAD   16
#define DK      64
#define BATCH   2
#define SEQ     2048
#define M_TOT   (BATCH*SEQ)          // 4096
#define BHS     (BATCH*NHEAD*SEQ)    // 65536
#define OUT_E   ((size_t)M_TOT*D_MODEL)         // 4,194,304
#define ATT_E   ((size_t)BATCH*NHEAD*SEQ*SEQ)   // 134,217,728
#define NTILE   16                    // SEQ/128 column tiles per row

// Scratch (static device globals). Only dereferenced in device code or
// resolved with cudaGetSymbolAddress (host-shadow/ATS trap on GB300).
__device__ __align__(16) float g_q[OUT_E];
__device__ __align__(16) float g_k[OUT_E];
__device__ __align__(16) float g_v[OUT_E];
__device__ __align__(16) float g_ctx[OUT_E];
__device__ __align__(16) float g_attn[ATT_E];
__device__ float g_m[BHS];
__device__ float g_l[BHS];
// partial softmax stats: [z][bn_tile][row] (coalesced within a scores block)
__device__ float g_pm[(size_t)BATCH*NHEAD*NTILE*SEQ];
__device__ float g_pl[(size_t)BATCH*NHEAD*NTILE*SEQ];

static __device__ __forceinline__ uint32_t smem_u32(const void* p) {
    return (uint32_t)__cvta_generic_to_shared(p);
}

// fp32 -> (hi: truncated bf16, lo: bf16(x-hi)); 3-term product error ~2^-17.
static __device__ __forceinline__ void split_bf16(float x, __nv_bfloat16& hi, __nv_bfloat16& lo) {
    uint32_t u = __float_as_uint(x) & 0xFFFF0000u;
    hi = __ushort_as_bfloat16((unsigned short)(u >> 16));
    lo = __float2bfloat16(x - __uint_as_float(u));
}

#define MMA_BF16(Cr, Ar, B0, B1)                                               \
    asm volatile(                                                              \
        "mma.sync.aligned.m16n8k16.row.col.f32.bf16.bf16.f32 "                 \
        "{%0,%1,%2,%3},{%4,%5,%6,%7},{%8,%9},{%0,%1,%2,%3};"                   \
        : "+f"(Cr[0]), "+f"(Cr[1]), "+f"(Cr[2]), "+f"(Cr[3])                   \
        : "r"(Ar[0]), "r"(Ar[1]), "r"(Ar[2]), "r"(Ar[3]), "r"(B0), "r"(B1))

#define LDMATRIX_X4(R, addr)                                                   \
    asm volatile("ldmatrix.sync.aligned.m8n8.x4.shared.b16 {%0,%1,%2,%3}, [%4];" \
        : "=r"(R[0]), "=r"(R[1]), "=r"(R[2]), "=r"(R[3]) : "r"(addr))

#define LDMATRIX_X2(R, addr)                                                   \
    asm volatile("ldmatrix.sync.aligned.m8n8.x2.shared.b16 {%0,%1}, [%2];"     \
        : "=r"(R[0]), "=r"(R[1]) : "r"(addr))

#define LDMATRIX_X2_T(R, addr)                                                 \
    asm volatile("ldmatrix.sync.aligned.m8n8.x2.trans.shared.b16 {%0,%1}, [%2];" \
        : "=r"(R[0]), "=r"(R[1]) : "r"(addr))

static __device__ __forceinline__ void store_split4(__nv_bfloat16* dh, __nv_bfloat16* dl, float4 v) {
    __nv_bfloat16 h0,h1,h2,h3,l0,l1,l2,l3;
    split_bf16(v.x, h0, l0); split_bf16(v.y, h1, l1);
    split_bf16(v.z, h2, l2); split_bf16(v.w, h3, l3);
    ((__nv_bfloat162*)dh)[0] = __nv_bfloat162(h0, h1);
    ((__nv_bfloat162*)dh)[1] = __nv_bfloat162(h2, h3);
    ((__nv_bfloat162*)dl)[0] = __nv_bfloat162(l0, l1);
    ((__nv_bfloat162*)dl)[1] = __nv_bfloat162(l2, l3);
}

// ---------------------------------------------------------------------------
// Split-bf16 tensor-core GEMM: C[4096,1024] = A @ W + bias
// ---------------------------------------------------------------------------
__global__ __launch_bounds__(256, 2)
void gemm_bias_mma(const float* __restrict__ A, const float* __restrict__ W,
                   const float* __restrict__ bias, float* __restrict__ C)
{
    const int LDA = 40;
    const int LDB = 136;
    __shared__ __nv_bfloat16 Ah[128 * LDA], Al[128 * LDA];
    __shared__ __nv_bfloat16 Bh[32 * LDB],  Bl[32 * LDB];

    int tid  = threadIdx.x;
    int lane = tid & 31, warp = tid >> 5;
    int bm = blockIdx.y * 128, bn = blockIdx.x * 128;
    int wm = (warp & 1) * 64, wn = (warp >> 1) * 32;

    float c[4][4][4];
#pragma unroll
    for (int mt = 0; mt < 4; mt++)
#pragma unroll
        for (int nt = 0; nt < 4; nt++)
#pragma unroll
            for (int e = 0; e < 4; e++) c[mt][nt][e] = 0.f;

    for (int k0 = 0; k0 < D_MODEL; k0 += 32) {
#pragma unroll
        for (int i = 0; i < 4; i++) {
            int idx = tid + i * 256;
            int row = idx >> 3, col = (idx & 7) << 2;
            float4 v = *(const float4*)(A + (size_t)(bm + row) * D_MODEL + k0 + col);
            store_split4(&Ah[row * LDA + col], &Al[row * LDA + col], v);
        }
#pragma unroll
        for (int i = 0; i < 4; i++) {
            int idx = tid + i * 256;
            int row = idx >> 5, col = (idx & 31) << 2;
            float4 v = *(const float4*)(W + (size_t)(k0 + row) * D_MODEL + bn + col);
            store_split4(&Bh[row * LDB + col], &Bl[row * LDB + col], v);
        }
        __syncthreads();

#pragma unroll
        for (int ks = 0; ks < 2; ks++) {
            int kb = ks * 16;
            uint32_t ah[4][4], al[4][4];
            {
                int grp = lane >> 3, r = lane & 7;
                int arow = wm + (grp & 1) * 8 + r;
                int acol = kb + ((grp & 2) ? 8 : 0);
#pragma unroll
                for (int mt = 0; mt < 4; mt++) {
                    LDMATRIX_X4(ah[mt], smem_u32(&Ah[(arow + mt * 16) * LDA + acol]));
                    LDMATRIX_X4(al[mt], smem_u32(&Al[(arow + mt * 16) * LDA + acol]));
                }
            }
            uint32_t bh[4][2], bl[4][2];
            {
                int brow = kb + ((lane >> 3) & 1) * 8 + (lane & 7);
#pragma unroll
                for (int nt = 0; nt < 4; nt++) {
                    int bcol = wn + nt * 8;
                    LDMATRIX_X2_T(bh[nt], smem_u32(&Bh[brow * LDB + bcol]));
                    LDMATRIX_X2_T(bl[nt], smem_u32(&Bl[brow * LDB + bcol]));
                }
            }
#pragma unroll
            for (int mt = 0; mt < 4; mt++)
#pragma unroll
                for (int nt = 0; nt < 4; nt++) {
                    MMA_BF16(c[mt][nt], ah[mt], bh[nt][0], bh[nt][1]);
                    MMA_BF16(c[mt][nt], ah[mt], bl[nt][0], bl[nt][1]);
                    MMA_BF16(c[mt][nt], al[mt], bh[nt][0], bh[nt][1]);
                }
        }
        __syncthreads();
    }

#pragma unroll
    for (int mt = 0; mt < 4; mt++)
#pragma unroll
        for (int nt = 0; nt < 4; nt++) {
            int row0 = bm + wm + mt * 16 + (lane >> 2);
            int col  = bn + wn + nt * 8 + (lane & 3) * 2;
            float b0 = bias[col], b1 = bias[col + 1];
            *(float2*)(C + (size_t)row0 * D_MODEL + col) =
                make_float2(c[mt][nt][0] + b0, c[mt][nt][1] + b1);
            *(float2*)(C + (size_t)(row0 + 8) * D_MODEL + col) =
                make_float2(c[mt][nt][2] + b0, c[mt][nt][3] + b1);
        }
}

// ---------------------------------------------------------------------------
// Scores + fused partial softmax stats.
// Tile [128q x 128k] = (1/8) Q·K^T (split-bf16). After the mma loop each block
// reduces its own tile: per-row partial max m_t and sumexp l_t, written to
// g_pm/g_pl[z][bn_tile][row]. Raw scaled scores still written to attn.
// ---------------------------------------------------------------------------
__global__ __launch_bounds__(256, 2)
void scores_mma(const float* __restrict__ qg, const float* __restrict__ kg,
                float* __restrict__ attn)
{
    extern __shared__ __nv_bfloat16 sm_s[];
    const int LD = 72;
    __nv_bfloat16* Qh = sm_s;
    __nv_bfloat16* Ql = Qh + 128 * LD;
    __nv_bfloat16* Kh = Ql + 128 * LD;
    __nv_bfloat16* Kl = Kh + 128 * LD;
    float* red_m = (float*)(Kl + 128 * LD);   // [128][4]
    float* red_l = red_m + 128 * 4;           // [128][4]

    int tid = threadIdx.x, lane = tid & 31, warp = tid >> 5;
    int z = blockIdx.z, b = z >> 4, h = z & 15;
    int bm = blockIdx.y * 128, bn = blockIdx.x * 128;
    int wm = (warp & 1) * 64, wn = (warp >> 1) * 32;
    int nw = warp >> 1;                       // n-warp index 0..3

    const float* qb = qg + (size_t)b * SEQ * D_MODEL + h * DK;
    const float* kb = kg + (size_t)b * SEQ * D_MODEL + h * DK;

#pragma unroll
    for (int i = 0; i < 8; i++) {
        int idx = tid + i * 256;
        int row = idx >> 4, col = (idx & 15) << 2;
        float4 v = *(const float4*)(qb + (size_t)(bm + row) * D_MODEL + col);
        store_split4(&Qh[row * LD + col], &Ql[row * LD + col], v);
        float4 w = *(const float4*)(kb + (size_t)(bn + row) * D_MODEL + col);
        store_split4(&Kh[row * LD + col], &Kl[row * LD + col], w);
    }
    __syncthreads();

    float c[4][4][4];
#pragma unroll
    for (int mt = 0; mt < 4; mt++)
#pragma unroll
        for (int nt = 0; nt < 4; nt++)
#pragma unroll
            for (int e = 0; e < 4; e++) c[mt][nt][e] = 0.f;

#pragma unroll
    for (int ks = 0; ks < 4; ks++) {
        int kb16 = ks * 16;
        uint32_t ah[4][4], al[4][4];
        {
            int grp = lane >> 3, r = lane & 7;
            int arow = wm + (grp & 1) * 8 + r;
            int acol = kb16 + ((grp & 2) ? 8 : 0);
#pragma unroll
            for (int mt = 0; mt < 4; mt++) {
                LDMATRIX_X4(ah[mt], smem_u32(&Qh[(arow + mt * 16) * LD + acol]));
                LDMATRIX_X4(al[mt], smem_u32(&Ql[(arow + mt * 16) * LD + acol]));
            }
        }
        uint32_t bh[4][2], bl[4][2];
        {
            int nr = lane & 7;
            int bcol = kb16 + ((lane >> 3) & 1) * 8;
#pragma unroll
            for (int nt = 0; nt < 4; nt++) {
                int nrow = wn + nt * 8 + nr;
                LDMATRIX_X2(bh[nt], smem_u32(&Kh[nrow * LD + bcol]));
                LDMATRIX_X2(bl[nt], smem_u32(&Kl[nrow * LD + bcol]));
            }
        }
#pragma unroll
        for (int mt = 0; mt < 4; mt++)
#pragma unroll
            for (int nt = 0; nt < 4; nt++) {
                MMA_BF16(c[mt][nt], ah[mt], bh[nt][0], bh[nt][1]);
                MMA_BF16(c[mt][nt], ah[mt], bl[nt][0], bl[nt][1]);
                MMA_BF16(c[mt][nt], al[mt], bh[nt][0], bh[nt][1]);
            }
    }

    // scale in place
    const float scale = 0.125f;
#pragma unroll
    for (int mt = 0; mt < 4; mt++)
#pragma unroll
        for (int nt = 0; nt < 4; nt++)
#pragma unroll
            for (int e = 0; e < 4; e++) c[mt][nt][e] *= scale;

    int rq = lane >> 2;               // 0..7
    bool qlead = (lane & 3) == 0;

    // pass 1: per-row tile max
#pragma unroll
    for (int mt = 0; mt < 4; mt++) {
        float m0 = -1e30f, m1 = -1e30f;
#pragma unroll
        for (int nt = 0; nt < 4; nt++) {
            m0 = fmaxf(m0, fmaxf(c[mt][nt][0], c[mt][nt][1]));
            m1 = fmaxf(m1, fmaxf(c[mt][nt][2], c[mt][nt][3]));
        }
        m0 = fmaxf(m0, __shfl_xor_sync(0xffffffffu, m0, 1));
        m0 = fmaxf(m0, __shfl_xor_sync(0xffffffffu, m0, 2));
        m1 = fmaxf(m1, __shfl_xor_sync(0xffffffffu, m1, 1));
        m1 = fmaxf(m1, __shfl_xor_sync(0xffffffffu, m1, 2));
        if (qlead) {
            red_m[(wm + mt * 16 + rq) * 4 + nw]     = m0;
            red_m[(wm + mt * 16 + 8 + rq) * 4 + nw] = m1;
        }
    }
    __syncthreads();

    // pass 2: per-row tile sumexp (with the block-wide row max)
#pragma unroll
    for (int mt = 0; mt < 4; mt++) {
        int r0 = wm + mt * 16 + rq, r1 = r0 + 8;
        float M0 = fmaxf(fmaxf(red_m[r0*4+0], red_m[r0*4+1]), fmaxf(red_m[r0*4+2], red_m[r0*4+3]));
        float M1 = fmaxf(fmaxf(red_m[r1*4+0], red_m[r1*4+1]), fmaxf(red_m[r1*4+2], red_m[r1*4+3]));
        float s0 = 0.f, s1 = 0.f;
#pragma unroll
        for (int nt = 0; nt < 4; nt++) {
            s0 += __expf(c[mt][nt][0] - M0) + __expf(c[mt][nt][1] - M0);
            s1 += __expf(c[mt][nt][2] - M1) + __expf(c[mt][nt][3] - M1);
        }
        s0 += __shfl_xor_sync(0xffffffffu, s0, 1);
        s0 += __shfl_xor_sync(0xffffffffu, s0, 2);
        s1 += __shfl_xor_sync(0xffffffffu, s1, 1);
        s1 += __shfl_xor_sync(0xffffffffu, s1, 2);
        if (qlead) {
            red_l[r0 * 4 + nw] = s0;
            red_l[r1 * 4 + nw] = s1;
        }
    }
    __syncthreads();

    if (tid < 128) {
        int r = tid;
        float M = fmaxf(fmaxf(red_m[r*4+0], red_m[r*4+1]), fmaxf(red_m[r*4+2], red_m[r*4+3]));
        float L = red_l[r*4+0] + red_l[r*4+1] + red_l[r*4+2] + red_l[r*4+3];
        size_t off = ((size_t)z * NTILE + blockIdx.x) * SEQ + bm + r;
        g_pm[off] = M;
        g_pl[off] = L;
    }

    // write scaled raw scores
    float* ab = attn + (size_t)z * SEQ * SEQ;
#pragma unroll
    for (int mt = 0; mt < 4; mt++)
#pragma unroll
        for (int nt = 0; nt < 4; nt++) {
            int row0 = bm + wm + mt * 16 + (lane >> 2);
            int col  = bn + wn + nt * 8 + (lane & 3) * 2;
            *(float2*)(ab + (size_t)row0 * SEQ + col) =
                make_float2(c[mt][nt][0], c[mt][nt][1]);
            *(float2*)(ab + (size_t)(row0 + 8) * SEQ + col) =
                make_float2(c[mt][nt][2], c[mt][nt][3]);
        }
}

// ---------------------------------------------------------------------------
// Combine partial stats: per row, logsumexp-merge the 16 column-tile partials.
// ---------------------------------------------------------------------------
__global__ __launch_bounds__(256)
void stats_combine(const float* __restrict__ pm, const float* __restrict__ pl)
{
    int R = blockIdx.x * 256 + threadIdx.x;     // 0..BHS-1
    int z = R >> 11, r = R & (SEQ - 1);
    size_t base = (size_t)z * NTILE * SEQ + r;

    float mv[NTILE];
    float M = -1e30f;
#pragma unroll
    for (int t = 0; t < NTILE; t++) {
        mv[t] = pm[base + (size_t)t * SEQ];
        M = fmaxf(M, mv[t]);
    }
    float L = 0.f;
#pragma unroll
    for (int t = 0; t < NTILE; t++)
        L += pl[base + (size_t)t * SEQ] * __expf(mv[t] - M);
    g_m[R] = M;
    g_l[R] = L;
}

// ---------------------------------------------------------------------------
// Context via mma (unchanged math; 2 CTAs/SM).
// ---------------------------------------------------------------------------
__global__ __launch_bounds__(256, 2)
void context_mma(float* __restrict__ attn, const float* __restrict__ vg,
                 float* __restrict__ ctx)
{
    extern __shared__ char sm_raw[];
    const int LD = 72;
    __nv_bfloat16* Ph = (__nv_bfloat16*)sm_raw;
    __nv_bfloat16* Pl = Ph + 128 * LD;
    __nv_bfloat16* Vh = Pl + 128 * LD;
    __nv_bfloat16* Vl = Vh + 64 * LD;
    float* mrow  = (float*)(Vl + 64 * LD);
    float* rlrow = mrow + 128;

    int tid = threadIdx.x, lane = tid & 31, warp = tid >> 5;
    int z = blockIdx.y, b = z >> 4, h = z & 15;
    int bm = blockIdx.x * 128;
    int wm = (warp & 1) * 64, wn = (warp >> 1) * 16;

    if (tid < 128) {
        mrow[tid]  = g_m[(size_t)z * SEQ + bm + tid];
        rlrow[tid] = 1.0f / g_l[(size_t)z * SEQ + bm + tid];
    }
    __syncthreads();

    float* ab = attn + (size_t)z * SEQ * SEQ;
    const float* vb = vg + (size_t)b * SEQ * D_MODEL + h * DK;

    float c[4][2][4];
#pragma unroll
    for (int mt = 0; mt < 4; mt++)
#pragma unroll
        for (int nt = 0; nt < 2; nt++)
#pragma unroll
            for (int e = 0; e < 4; e++) c[mt][nt][e] = 0.f;

    for (int k0 = 0; k0 < SEQ; k0 += 64) {
#pragma unroll
        for (int i = 0; i < 8; i++) {
            int idx = tid + i * 256;
            int row = idx >> 4, col = (idx & 15) << 2;
            float* gp = ab + (size_t)(bm + row) * SEQ + k0 + col;
            float4 sv = *(float4*)gp;
            float m = mrow[row], rl = rlrow[row];
            sv.x = __expf(sv.x - m) * rl;
            sv.y = __expf(sv.y - m) * rl;
            sv.z = __expf(sv.z - m) * rl;
            sv.w = __expf(sv.w - m) * rl;
            *(float4*)gp = sv;
            store_split4(&Ph[row * LD + col], &Pl[row * LD + col], sv);
        }
#pragma unroll
        for (int i = 0; i < 4; i++) {
            int idx = tid + i * 256;
            int row = idx >> 4, col = (idx & 15) << 2;
            float4 v = *(const float4*)(vb + (size_t)(k0 + row) * D_MODEL + col);
            store_split4(&Vh[row * LD + col], &Vl[row * LD + col], v);
        }
        __syncthreads();

#pragma unroll
        for (int ks = 0; ks < 4; ks++) {
            int kb16 = ks * 16;
            uint32_t ah[4][4], al[4][4];
            {
                int grp = lane >> 3, r = lane & 7;
                int arow = wm + (grp & 1) * 8 + r;
                int acol = kb16 + ((grp & 2) ? 8 : 0);
#pragma unroll
                for (int mt = 0; mt < 4; mt++) {
                    LDMATRIX_X4(ah[mt], smem_u32(&Ph[(arow + mt * 16) * LD + acol]));
                    LDMATRIX_X4(al[mt], smem_u32(&Pl[(arow + mt * 16) * LD + acol]));
                }
            }
            uint32_t bh[2][2], bl[2][2];
            {
                int brow = kb16 + ((lane >> 3) & 1) * 8 + (lane & 7);
#pragma unroll
                for (int nt = 0; nt < 2; nt++) {
                    int bcol = wn + nt * 8;
                    LDMATRIX_X2_T(bh[nt], smem_u32(&Vh[brow * LD + bcol]));
                    LDMATRIX_X2_T(bl[nt], smem_u32(&Vl[brow * LD + bcol]));
                }
            }
#pragma unroll
            for (int mt = 0; mt < 4; mt++)
#pragma unroll
                for (int nt = 0; nt < 2; nt++) {
                    MMA_BF16(c[mt][nt], ah[mt], bh[nt][0], bh[nt][1]);
                    MMA_BF16(c[mt][nt], ah[mt], bl[nt][0], bl[nt][1]);
                    MMA_BF16(c[mt][nt], al[mt], bh[nt][0], bh[nt][1]);
                }
        }
        __syncthreads();
    }

#pragma unroll
    for (int mt = 0; mt < 4; mt++)
#pragma unroll
        for (int nt = 0; nt < 2; nt++) {
            int row0 = bm + wm + mt * 16 + (lane >> 2);
            int col  = wn + nt * 8 + (lane & 3) * 2;
            *(float2*)(ctx + (size_t)(b * SEQ + row0) * D_MODEL + h * DK + col) =
                make_float2(c[mt][nt][0], c[mt][nt][1]);
            *(float2*)(ctx + (size_t)(b * SEQ + row0 + 8) * D_MODEL + h * DK + col) =
                make_float2(c[mt][nt][2], c[mt][nt][3]);
        }
}

// ---------------------------------------------------------------------------
extern "C" void kernel_launch(void* const* d_in, const int* in_sizes, int n_in,
                              void* d_out, int out_size)
{
    const float* Q   = (const float*)d_in[0];
    const float* K   = (const float*)d_in[1];
    const float* V   = (const float*)d_in[2];
    const float* Wq  = (const float*)d_in[3];
    const float* bq  = (const float*)d_in[4];
    const float* Wk  = (const float*)d_in[5];
    const float* bk  = (const float*)d_in[6];
    const float* Wv  = (const float*)d_in[7];
    const float* bv  = (const float*)d_in[8];
    const float* Wfc = (const float*)d_in[9];
    const float* bfc = (const float*)d_in[10];

    float* out = (float*)d_out;

    void *pq, *pk, *pv, *pc, *pa, *ppm, *ppl;
    cudaGetSymbolAddress(&pq, g_q);
    cudaGetSymbolAddress(&pk, g_k);
    cudaGetSymbolAddress(&pv, g_v);
    cudaGetSymbolAddress(&pc, g_ctx);
    cudaGetSymbolAddress(&pa, g_attn);
    cudaGetSymbolAddress(&ppm, g_pm);
    cudaGetSymbolAddress(&ppl, g_pl);
    float* dq   = (float*)pq;
    float* dk   = (float*)pk;
    float* dv   = (float*)pv;
    float* dctx = (float*)pc;

    float* attn = ((size_t)out_size >= OUT_E + ATT_E) ? (out + OUT_E)
                                                      : (float*)pa;

    const int SC_SMEM  = 4 * 128 * 72 * 2 + 2 * 128 * 4 * 4;   // 77,824 B
    const int CTX_SMEM = (2*128*72 + 2*64*72) * 2 + 2*128*4;   // 56,320 B
    cudaFuncSetAttribute(scores_mma, cudaFuncAttributeMaxDynamicSharedMemorySize, SC_SMEM);
    cudaFuncSetAttribute(context_mma, cudaFuncAttributeMaxDynamicSharedMemorySize, CTX_SMEM);

    dim3 gemm_grid(D_MODEL / 128, M_TOT / 128);        // (8, 32)
    gemm_bias_mma<<<gemm_grid, 256>>>(Q, Wq, bq, dq);
    gemm_bias_mma<<<gemm_grid, 256>>>(K, Wk, bk, dk);
    gemm_bias_mma<<<gemm_grid, 256>>>(V, Wv, bv, dv);

    dim3 sc_grid(SEQ / 128, SEQ / 128, BATCH * NHEAD); // (16, 16, 32)
    scores_mma<<<sc_grid, 256, SC_SMEM>>>(dq, dk, attn);

    stats_combine<<<BHS / 256, 256>>>((const float*)ppm, (const float*)ppl);

    dim3 ctx_grid(SEQ / 128, BATCH * NHEAD);           // (16, 32)
    context_mma<<<ctx_grid, 256, CTX_SMEM>>>(attn, dv, dctx);

    gemm_bias_mma<<<gemm_grid, 256>>>(dctx, Wfc, bfc, out);
}

// round 16
// speedup vs baseline: 2.1204x; 1.0165x over previous
#include <cuda_runtime.h>
#include <cuda_bf16.h>
#include <math.h>
#include <stdint.h>

#define D_MODEL 1024
#define NHEAD   16
#define DK      64
#define BATCH   2
#define SEQ     2048
#define M_TOT   (BATCH*SEQ)          // 4096
#define BHS     (BATCH*NHEAD*SEQ)    // 65536
#define OUT_E   ((size_t)M_TOT*D_MODEL)         // 4,194,304
#define ATT_E   ((size_t)BATCH*NHEAD*SEQ*SEQ)   // 134,217,728
#define NTILE   16                    // SEQ/128 column tiles per row

// Scratch (static device globals). Only dereferenced in device code or
// resolved with cudaGetSymbolAddress (host-shadow/ATS trap on GB300).
__device__ __align__(16) float g_q[OUT_E];
__device__ __align__(16) float g_k[OUT_E];
__device__ __align__(16) float g_v[OUT_E];
__device__ __align__(16) float g_ctx[OUT_E];
__device__ __align__(16) float g_attn[ATT_E];
__device__ float g_m[BHS];
__device__ float g_l[BHS];
__device__ float g_pm[(size_t)BATCH*NHEAD*NTILE*SEQ];
__device__ float g_pl[(size_t)BATCH*NHEAD*NTILE*SEQ];

static __device__ __forceinline__ uint32_t smem_u32(const void* p) {
    return (uint32_t)__cvta_generic_to_shared(p);
}

// fp32 -> (hi: truncated bf16, lo: bf16(x-hi)); 3-term product error ~2^-17.
static __device__ __forceinline__ void split_bf16(float x, __nv_bfloat16& hi, __nv_bfloat16& lo) {
    uint32_t u = __float_as_uint(x) & 0xFFFF0000u;
    hi = __ushort_as_bfloat16((unsigned short)(u >> 16));
    lo = __float2bfloat16(x - __uint_as_float(u));
}

#define MMA_BF16(Cr, Ar, B0, B1)                                               \
    asm volatile(                                                              \
        "mma.sync.aligned.m16n8k16.row.col.f32.bf16.bf16.f32 "                 \
        "{%0,%1,%2,%3},{%4,%5,%6,%7},{%8,%9},{%0,%1,%2,%3};"                   \
        : "+f"(Cr[0]), "+f"(Cr[1]), "+f"(Cr[2]), "+f"(Cr[3])                   \
        : "r"(Ar[0]), "r"(Ar[1]), "r"(Ar[2]), "r"(Ar[3]), "r"(B0), "r"(B1))

#define LDMATRIX_X4(R, addr)                                                   \
    asm volatile("ldmatrix.sync.aligned.m8n8.x4.shared.b16 {%0,%1,%2,%3}, [%4];" \
        : "=r"(R[0]), "=r"(R[1]), "=r"(R[2]), "=r"(R[3]) : "r"(addr))

#define LDMATRIX_X2(R, addr)                                                   \
    asm volatile("ldmatrix.sync.aligned.m8n8.x2.shared.b16 {%0,%1}, [%2];"     \
        : "=r"(R[0]), "=r"(R[1]) : "r"(addr))

#define LDMATRIX_X2_T(R, addr)                                                 \
    asm volatile("ldmatrix.sync.aligned.m8n8.x2.trans.shared.b16 {%0,%1}, [%2];" \
        : "=r"(R[0]), "=r"(R[1]) : "r"(addr))

#define CP_ASYNC16(saddr, gptr)                                                \
    asm volatile("cp.async.cg.shared.global [%0], [%1], 16;"                   \
        :: "r"(saddr), "l"(gptr))
#define CP_COMMIT()  asm volatile("cp.async.commit_group;")
#define CP_WAIT(n)   asm volatile("cp.async.wait_group %0;" :: "n"(n))

static __device__ __forceinline__ void store_split4(__nv_bfloat16* dh, __nv_bfloat16* dl, float4 v) {
    __nv_bfloat16 h0,h1,h2,h3,l0,l1,l2,l3;
    split_bf16(v.x, h0, l0); split_bf16(v.y, h1, l1);
    split_bf16(v.z, h2, l2); split_bf16(v.w, h3, l3);
    ((__nv_bfloat162*)dh)[0] = __nv_bfloat162(h0, h1);
    ((__nv_bfloat162*)dh)[1] = __nv_bfloat162(h2, h3);
    ((__nv_bfloat162*)dl)[0] = __nv_bfloat162(l0, l1);
    ((__nv_bfloat162*)dl)[1] = __nv_bfloat162(l2, l3);
}

// ---------------------------------------------------------------------------
// Split-bf16 tensor-core GEMM with cp.async double-buffered staging.
// C[4096,1024] = A @ W + bias. BM=BN=128, BK=32, 256 thr, 8 warps 64x32.
// Raw fp32 tiles land in a 2-deep smem ring via cp.async while the previous
// iteration's mmas run; convert (split-bf16) reads smem, not registers.
// ---------------------------------------------------------------------------
__global__ __launch_bounds__(256, 2)
void gemm_bias_mma(const float* __restrict__ A, const float* __restrict__ W,
                   const float* __restrict__ bias, float* __restrict__ C)
{
    const int LDA = 40;
    const int LDB = 136;
    extern __shared__ char smem_dyn[];
    float* Araw = (float*)smem_dyn;                        // 2 x 128x32
    float* Wraw = Araw + 2 * 4096;                         // 2 x 32x128
    __nv_bfloat16* Ah = (__nv_bfloat16*)(Wraw + 2 * 4096); // 128*LDA
    __nv_bfloat16* Al = Ah + 128 * LDA;
    __nv_bfloat16* Bh = Al + 128 * LDA;                    // 32*LDB
    __nv_bfloat16* Bl = Bh + 32 * LDB;

    int tid  = threadIdx.x;
    int lane = tid & 31, warp = tid >> 5;
    int bm = blockIdx.y * 128, bn = blockIdx.x * 128;
    int wm = (warp & 1) * 64, wn = (warp >> 1) * 32;

    // per-thread staging coordinates (4 x 16B each for A and W)
    int a_row[4], a_col[4], w_row[4], w_col[4];
#pragma unroll
    for (int i = 0; i < 4; i++) {
        int idx = tid + i * 256;
        a_row[i] = idx >> 3;  a_col[i] = (idx & 7) << 2;
        w_row[i] = idx >> 5;  w_col[i] = (idx & 31) << 2;
    }

    // prologue: stage k0=0 into buffer 0
#pragma unroll
    for (int i = 0; i < 4; i++) {
        CP_ASYNC16(smem_u32(&Araw[a_row[i] * 32 + a_col[i]]),
                   A + (size_t)(bm + a_row[i]) * D_MODEL + a_col[i]);
        CP_ASYNC16(smem_u32(&Wraw[w_row[i] * 128 + w_col[i]]),
                   W + (size_t)w_row[i] * D_MODEL + bn + w_col[i]);
    }
    CP_COMMIT();

    float c[4][4][4];
#pragma unroll
    for (int mt = 0; mt < 4; mt++)
#pragma unroll
        for (int nt = 0; nt < 4; nt++)
#pragma unroll
            for (int e = 0; e < 4; e++) c[mt][nt][e] = 0.f;

    for (int it = 0; it < 32; it++) {
        int buf  = it & 1;
        // issue next stage
        if (it + 1 < 32) {
            int nb = (it + 1) & 1;
            int k0 = (it + 1) * 32;
#pragma unroll
            for (int i = 0; i < 4; i++) {
                CP_ASYNC16(smem_u32(&Araw[nb * 4096 + a_row[i] * 32 + a_col[i]]),
                           A + (size_t)(bm + a_row[i]) * D_MODEL + k0 + a_col[i]);
                CP_ASYNC16(smem_u32(&Wraw[nb * 4096 + w_row[i] * 128 + w_col[i]]),
                           W + (size_t)(k0 + w_row[i]) * D_MODEL + bn + w_col[i]);
            }
            CP_COMMIT();
            CP_WAIT(1);
        } else {
            CP_WAIT(0);
        }
        __syncthreads();   // raw(it) visible to all; prev iter's mmas done

        // convert raw -> split bf16
#pragma unroll
        for (int i = 0; i < 4; i++) {
            float4 v = *(float4*)&Araw[buf * 4096 + a_row[i] * 32 + a_col[i]];
            store_split4(&Ah[a_row[i] * LDA + a_col[i]], &Al[a_row[i] * LDA + a_col[i]], v);
            float4 w = *(float4*)&Wraw[buf * 4096 + w_row[i] * 128 + w_col[i]];
            store_split4(&Bh[w_row[i] * LDB + w_col[i]], &Bl[w_row[i] * LDB + w_col[i]], w);
        }
        __syncthreads();   // bf16 tiles ready

#pragma unroll
        for (int ks = 0; ks < 2; ks++) {
            int kb = ks * 16;
            uint32_t ah[4][4], al[4][4];
            {
                int grp = lane >> 3, r = lane & 7;
                int arow = wm + (grp & 1) * 8 + r;
                int acol = kb + ((grp & 2) ? 8 : 0);
#pragma unroll
                for (int mt = 0; mt < 4; mt++) {
                    LDMATRIX_X4(ah[mt], smem_u32(&Ah[(arow + mt * 16) * LDA + acol]));
                    LDMATRIX_X4(al[mt], smem_u32(&Al[(arow + mt * 16) * LDA + acol]));
                }
            }
            uint32_t bh[4][2], bl[4][2];
            {
                int brow = kb + ((lane >> 3) & 1) * 8 + (lane & 7);
#pragma unroll
                for (int nt = 0; nt < 4; nt++) {
                    int bcol = wn + nt * 8;
                    LDMATRIX_X2_T(bh[nt], smem_u32(&Bh[brow * LDB + bcol]));
                    LDMATRIX_X2_T(bl[nt], smem_u32(&Bl[brow * LDB + bcol]));
                }
            }
#pragma unroll
            for (int mt = 0; mt < 4; mt++)
#pragma unroll
                for (int nt = 0; nt < 4; nt++) {
                    MMA_BF16(c[mt][nt], ah[mt], bh[nt][0], bh[nt][1]);
                    MMA_BF16(c[mt][nt], ah[mt], bl[nt][0], bl[nt][1]);
                    MMA_BF16(c[mt][nt], al[mt], bh[nt][0], bh[nt][1]);
                }
        }
        __syncthreads();   // bf16 consumed; safe to convert next iter
    }

#pragma unroll
    for (int mt = 0; mt < 4; mt++)
#pragma unroll
        for (int nt = 0; nt < 4; nt++) {
            int row0 = bm + wm + mt * 16 + (lane >> 2);
            int col  = bn + wn + nt * 8 + (lane & 3) * 2;
            float b0 = bias[col], b1 = bias[col + 1];
            *(float2*)(C + (size_t)row0 * D_MODEL + col) =
                make_float2(c[mt][nt][0] + b0, c[mt][nt][1] + b1);
            *(float2*)(C + (size_t)(row0 + 8) * D_MODEL + col) =
                make_float2(c[mt][nt][2] + b0, c[mt][nt][3] + b1);
        }
}

// ---------------------------------------------------------------------------
// Scores + fused partial softmax stats (validated R14).
// ---------------------------------------------------------------------------
__global__ __launch_bounds__(256, 2)
void scores_mma(const float* __restrict__ qg, const float* __restrict__ kg,
                float* __restrict__ attn)
{
    extern __shared__ __nv_bfloat16 sm_s[];
    const int LD = 72;
    __nv_bfloat16* Qh = sm_s;
    __nv_bfloat16* Ql = Qh + 128 * LD;
    __nv_bfloat16* Kh = Ql + 128 * LD;
    __nv_bfloat16* Kl = Kh + 128 * LD;
    float* red_m = (float*)(Kl + 128 * LD);   // [128][4]
    float* red_l = red_m + 128 * 4;           // [128][4]

    int tid = threadIdx.x, lane = tid & 31, warp = tid >> 5;
    int z = blockIdx.z, b = z >> 4, h = z & 15;
    int bm = blockIdx.y * 128, bn = blockIdx.x * 128;
    int wm = (warp & 1) * 64, wn = (warp >> 1) * 32;
    int nw = warp >> 1;

    const float* qb = qg + (size_t)b * SEQ * D_MODEL + h * DK;
    const float* kb = kg + (size_t)b * SEQ * D_MODEL + h * DK;

#pragma unroll
    for (int i = 0; i < 8; i++) {
        int idx = tid + i * 256;
        int row = idx >> 4, col = (idx & 15) << 2;
        float4 v = *(const float4*)(qb + (size_t)(bm + row) * D_MODEL + col);
        store_split4(&Qh[row * LD + col], &Ql[row * LD + col], v);
        float4 w = *(const float4*)(kb + (size_t)(bn + row) * D_MODEL + col);
        store_split4(&Kh[row * LD + col], &Kl[row * LD + col], w);
    }
    __syncthreads();

    float c[4][4][4];
#pragma unroll
    for (int mt = 0; mt < 4; mt++)
#pragma unroll
        for (int nt = 0; nt < 4; nt++)
#pragma unroll
            for (int e = 0; e < 4; e++) c[mt][nt][e] = 0.f;

#pragma unroll
    for (int ks = 0; ks < 4; ks++) {
        int kb16 = ks * 16;
        uint32_t ah[4][4], al[4][4];
        {
            int grp = lane >> 3, r = lane & 7;
            int arow = wm + (grp & 1) * 8 + r;
            int acol = kb16 + ((grp & 2) ? 8 : 0);
#pragma unroll
            for (int mt = 0; mt < 4; mt++) {
                LDMATRIX_X4(ah[mt], smem_u32(&Qh[(arow + mt * 16) * LD + acol]));
                LDMATRIX_X4(al[mt], smem_u32(&Ql[(arow + mt * 16) * LD + acol]));
            }
        }
        uint32_t bh[4][2], bl[4][2];
        {
            int nr = lane & 7;
            int bcol = kb16 + ((lane >> 3) & 1) * 8;
#pragma unroll
            for (int nt = 0; nt < 4; nt++) {
                int nrow = wn + nt * 8 + nr;
                LDMATRIX_X2(bh[nt], smem_u32(&Kh[nrow * LD + bcol]));
                LDMATRIX_X2(bl[nt], smem_u32(&Kl[nrow * LD + bcol]));
            }
        }
#pragma unroll
        for (int mt = 0; mt < 4; mt++)
#pragma unroll
            for (int nt = 0; nt < 4; nt++) {
                MMA_BF16(c[mt][nt], ah[mt], bh[nt][0], bh[nt][1]);
                MMA_BF16(c[mt][nt], ah[mt], bl[nt][0], bl[nt][1]);
                MMA_BF16(c[mt][nt], al[mt], bh[nt][0], bh[nt][1]);
            }
    }

    const float scale = 0.125f;
#pragma unroll
    for (int mt = 0; mt < 4; mt++)
#pragma unroll
        for (int nt = 0; nt < 4; nt++)
#pragma unroll
            for (int e = 0; e < 4; e++) c[mt][nt][e] *= scale;

    int rq = lane >> 2;
    bool qlead = (lane & 3) == 0;

#pragma unroll
    for (int mt = 0; mt < 4; mt++) {
        float m0 = -1e30f, m1 = -1e30f;
#pragma unroll
        for (int nt = 0; nt < 4; nt++) {
            m0 = fmaxf(m0, fmaxf(c[mt][nt][0], c[mt][nt][1]));
            m1 = fmaxf(m1, fmaxf(c[mt][nt][2], c[mt][nt][3]));
        }
        m0 = fmaxf(m0, __shfl_xor_sync(0xffffffffu, m0, 1));
        m0 = fmaxf(m0, __shfl_xor_sync(0xffffffffu, m0, 2));
        m1 = fmaxf(m1, __shfl_xor_sync(0xffffffffu, m1, 1));
        m1 = fmaxf(m1, __shfl_xor_sync(0xffffffffu, m1, 2));
        if (qlead) {
            red_m[(wm + mt * 16 + rq) * 4 + nw]     = m0;
            red_m[(wm + mt * 16 + 8 + rq) * 4 + nw] = m1;
        }
    }
    __syncthreads();

#pragma unroll
    for (int mt = 0; mt < 4; mt++) {
        int r0 = wm + mt * 16 + rq, r1 = r0 + 8;
        float M0 = fmaxf(fmaxf(red_m[r0*4+0], red_m[r0*4+1]), fmaxf(red_m[r0*4+2], red_m[r0*4+3]));
        float M1 = fmaxf(fmaxf(red_m[r1*4+0], red_m[r1*4+1]), fmaxf(red_m[r1*4+2], red_m[r1*4+3]));
        float s0 = 0.f, s1 = 0.f;
#pragma unroll
        for (int nt = 0; nt < 4; nt++) {
            s0 += __expf(c[mt][nt][0] - M0) + __expf(c[mt][nt][1] - M0);
            s1 += __expf(c[mt][nt][2] - M1) + __expf(c[mt][nt][3] - M1);
        }
        s0 += __shfl_xor_sync(0xffffffffu, s0, 1);
        s0 += __shfl_xor_sync(0xffffffffu, s0, 2);
        s1 += __shfl_xor_sync(0xffffffffu, s1, 1);
        s1 += __shfl_xor_sync(0xffffffffu, s1, 2);
        if (qlead) {
            red_l[r0 * 4 + nw] = s0;
            red_l[r1 * 4 + nw] = s1;
        }
    }
    __syncthreads();

    if (tid < 128) {
        int r = tid;
        float M = fmaxf(fmaxf(red_m[r*4+0], red_m[r*4+1]), fmaxf(red_m[r*4+2], red_m[r*4+3]));
        float L = red_l[r*4+0] + red_l[r*4+1] + red_l[r*4+2] + red_l[r*4+3];
        size_t off = ((size_t)z * NTILE + blockIdx.x) * SEQ + bm + r;
        g_pm[off] = M;
        g_pl[off] = L;
    }

    float* ab = attn + (size_t)z * SEQ * SEQ;
#pragma unroll
    for (int mt = 0; mt < 4; mt++)
#pragma unroll
        for (int nt = 0; nt < 4; nt++) {
            int row0 = bm + wm + mt * 16 + (lane >> 2);
            int col  = bn + wn + nt * 8 + (lane & 3) * 2;
            *(float2*)(ab + (size_t)row0 * SEQ + col) =
                make_float2(c[mt][nt][0], c[mt][nt][1]);
            *(float2*)(ab + (size_t)(row0 + 8) * SEQ + col) =
                make_float2(c[mt][nt][2], c[mt][nt][3]);
        }
}

// ---------------------------------------------------------------------------
__global__ __launch_bounds__(256)
void stats_combine(const float* __restrict__ pm, const float* __restrict__ pl)
{
    int R = blockIdx.x * 256 + threadIdx.x;
    int z = R >> 11, r = R & (SEQ - 1);
    size_t base = (size_t)z * NTILE * SEQ + r;

    float mv[NTILE];
    float M = -1e30f;
#pragma unroll
    for (int t = 0; t < NTILE; t++) {
        mv[t] = pm[base + (size_t)t * SEQ];
        M = fmaxf(M, mv[t]);
    }
    float L = 0.f;
#pragma unroll
    for (int t = 0; t < NTILE; t++)
        L += pl[base + (size_t)t * SEQ] * __expf(mv[t] - M);
    g_m[R] = M;
    g_l[R] = L;
}

// ---------------------------------------------------------------------------
// Context via mma (validated R14).
// ---------------------------------------------------------------------------
__global__ __launch_bounds__(256, 2)
void context_mma(float* __restrict__ attn, const float* __restrict__ vg,
                 float* __restrict__ ctx)
{
    extern __shared__ char sm_raw[];
    const int LD = 72;
    __nv_bfloat16* Ph = (__nv_bfloat16*)sm_raw;
    __nv_bfloat16* Pl = Ph + 128 * LD;
    __nv_bfloat16* Vh = Pl + 128 * LD;
    __nv_bfloat16* Vl = Vh + 64 * LD;
    float* mrow  = (float*)(Vl + 64 * LD);
    float* rlrow = mrow + 128;

    int tid = threadIdx.x, lane = tid & 31, warp = tid >> 5;
    int z = blockIdx.y, b = z >> 4, h = z & 15;
    int bm = blockIdx.x * 128;
    int wm = (warp & 1) * 64, wn = (warp >> 1) * 16;

    if (tid < 128) {
        mrow[tid]  = g_m[(size_t)z * SEQ + bm + tid];
        rlrow[tid] = 1.0f / g_l[(size_t)z * SEQ + bm + tid];
    }
    __syncthreads();

    float* ab = attn + (size_t)z * SEQ * SEQ;
    const float* vb = vg + (size_t)b * SEQ * D_MODEL + h * DK;

    float c[4][2][4];
#pragma unroll
    for (int mt = 0; mt < 4; mt++)
#pragma unroll
        for (int nt = 0; nt < 2; nt++)
#pragma unroll
            for (int e = 0; e < 4; e++) c[mt][nt][e] = 0.f;

    for (int k0 = 0; k0 < SEQ; k0 += 64) {
#pragma unroll
        for (int i = 0; i < 8; i++) {
            int idx = tid + i * 256;
            int row = idx >> 4, col = (idx & 15) << 2;
            float* gp = ab + (size_t)(bm + row) * SEQ + k0 + col;
            float4 sv = *(float4*)gp;
            float m = mrow[row], rl = rlrow[row];
            sv.x = __expf(sv.x - m) * rl;
            sv.y = __expf(sv.y - m) * rl;
            sv.z = __expf(sv.z - m) * rl;
            sv.w = __expf(sv.w - m) * rl;
            *(float4*)gp = sv;
            store_split4(&Ph[row * LD + col], &Pl[row * LD + col], sv);
        }
#pragma unroll
        for (int i = 0; i < 4; i++) {
            int idx = tid + i * 256;
            int row = idx >> 4, col = (idx & 15) << 2;
            float4 v = *(const float4*)(vb + (size_t)(k0 + row) * D_MODEL + col);
            store_split4(&Vh[row * LD + col], &Vl[row * LD + col], v);
        }
        __syncthreads();

#pragma unroll
        for (int ks = 0; ks < 4; ks++) {
            int kb16 = ks * 16;
            uint32_t ah[4][4], al[4][4];
            {
                int grp = lane >> 3, r = lane & 7;
                int arow = wm + (grp & 1) * 8 + r;
                int acol = kb16 + ((grp & 2) ? 8 : 0);
#pragma unroll
                for (int mt = 0; mt < 4; mt++) {
                    LDMATRIX_X4(ah[mt], smem_u32(&Ph[(arow + mt * 16) * LD + acol]));
                    LDMATRIX_X4(al[mt], smem_u32(&Pl[(arow + mt * 16) * LD + acol]));
                }
            }
            uint32_t bh[2][2], bl[2][2];
            {
                int brow = kb16 + ((lane >> 3) & 1) * 8 + (lane & 7);
#pragma unroll
                for (int nt = 0; nt < 2; nt++) {
                    int bcol = wn + nt * 8;
                    LDMATRIX_X2_T(bh[nt], smem_u32(&Vh[brow * LD + bcol]));
                    LDMATRIX_X2_T(bl[nt], smem_u32(&Vl[brow * LD + bcol]));
                }
            }
#pragma unroll
            for (int mt = 0; mt < 4; mt++)
#pragma unroll
                for (int nt = 0; nt < 2; nt++) {
                    MMA_BF16(c[mt][nt], ah[mt], bh[nt][0], bh[nt][1]);
                    MMA_BF16(c[mt][nt], ah[mt], bl[nt][0], bl[nt][1]);
                    MMA_BF16(c[mt][nt], al[mt], bh[nt][0], bh[nt][1]);
                }
        }
        __syncthreads();
    }

#pragma unroll
    for (int mt = 0; mt < 4; mt++)
#pragma unroll
        for (int nt = 0; nt < 2; nt++) {
            int row0 = bm + wm + mt * 16 + (lane >> 2);
            int col  = wn + nt * 8 + (lane & 3) * 2;
            *(float2*)(ctx + (size_t)(b * SEQ + row0) * D_MODEL + h * DK + col) =
                make_float2(c[mt][nt][0], c[mt][nt][1]);
            *(float2*)(ctx + (size_t)(b * SEQ + row0 + 8) * D_MODEL + h * DK + col) =
                make_float2(c[mt][nt][2], c[mt][nt][3]);
        }
}

// ---------------------------------------------------------------------------
extern "C" void kernel_launch(void* const* d_in, const int* in_sizes, int n_in,
                              void* d_out, int out_size)
{
    const float* Q   = (const float*)d_in[0];
    const float* K   = (const float*)d_in[1];
    const float* V   = (const float*)d_in[2];
    const float* Wq  = (const float*)d_in[3];
    const float* bq  = (const float*)d_in[4];
    const float* Wk  = (const float*)d_in[5];
    const float* bk  = (const float*)d_in[6];
    const float* Wv  = (const float*)d_in[7];
    const float* bv  = (const float*)d_in[8];
    const float* Wfc = (const float*)d_in[9];
    const float* bfc = (const float*)d_in[10];

    float* out = (float*)d_out;

    void *pq, *pk, *pv, *pc, *pa, *ppm, *ppl;
    cudaGetSymbolAddress(&pq, g_q);
    cudaGetSymbolAddress(&pk, g_k);
    cudaGetSymbolAddress(&pv, g_v);
    cudaGetSymbolAddress(&pc, g_ctx);
    cudaGetSymbolAddress(&pa, g_attn);
    cudaGetSymbolAddress(&ppm, g_pm);
    cudaGetSymbolAddress(&ppl, g_pl);
    float* dq   = (float*)pq;
    float* dk   = (float*)pk;
    float* dv   = (float*)pv;
    float* dctx = (float*)pc;

    float* attn = ((size_t)out_size >= OUT_E + ATT_E) ? (out + OUT_E)
                                                      : (float*)pa;

    const int GEMM_SMEM = (2*4096 + 2*4096) * 4 + (2*128*40 + 2*32*136) * 2; // 103,424 B
    const int SC_SMEM   = 4 * 128 * 72 * 2 + 2 * 128 * 4 * 4;                // 77,824 B
    const int CTX_SMEM  = (2*128*72 + 2*64*72) * 2 + 2*128*4;                // 56,320 B
    cudaFuncSetAttribute(gemm_bias_mma, cudaFuncAttributeMaxDynamicSharedMemorySize, GEMM_SMEM);
    cudaFuncSetAttribute(scores_mma, cudaFuncAttributeMaxDynamicSharedMemorySize, SC_SMEM);
    cudaFuncSetAttribute(context_mma, cudaFuncAttributeMaxDynamicSharedMemorySize, CTX_SMEM);

    dim3 gemm_grid(D_MODEL / 128, M_TOT / 128);        // (8, 32)
    gemm_bias_mma<<<gemm_grid, 256, GEMM_SMEM>>>(Q, Wq, bq, dq);
    gemm_bias_mma<<<gemm_grid, 256, GEMM_SMEM>>>(K, Wk, bk, dk);
    gemm_bias_mma<<<gemm_grid, 256, GEMM_SMEM>>>(V, Wv, bv, dv);

    dim3 sc_grid(SEQ / 128, SEQ / 128, BATCH * NHEAD); // (16, 16, 32)
    scores_mma<<<sc_grid, 256, SC_SMEM>>>(dq, dk, attn);

    stats_combine<<<BHS / 256, 256>>>((const float*)ppm, (const float*)ppl);

    dim3 ctx_grid(SEQ / 128, BATCH * NHEAD);           // (16, 32)
    context_mma<<<ctx_grid, 256, CTX_SMEM>>>(attn, dv, dctx);

    gemm_bias_mma<<<gemm_grid, 256, GEMM_SMEM>>>(dctx, Wfc, bfc, out);
}

// round 17
// speedup vs baseline: 2.5594x; 1.2070x over previous
#include <cuda_runtime.h>
#include <cuda_bf16.h>
#include <math.h>
#include <stdint.h>

#define D_MODEL 1024
#define NHEAD   16
#define DK      64
#define BATCH   2
#define SEQ     2048
#define M_TOT   (BATCH*SEQ)          // 4096
#define BHS     (BATCH*NHEAD*SEQ)    // 65536
#define OUT_E   ((size_t)M_TOT*D_MODEL)         // 4,194,304
#define ATT_E   ((size_t)BATCH*NHEAD*SEQ*SEQ)   // 134,217,728
#define NTILE   16                    // SEQ/128 column tiles per row

// Scratch (static device globals). Only dereferenced in device code or
// resolved with cudaGetSymbolAddress (host-shadow/ATS trap on GB300).
__device__ __align__(16) float g_q[OUT_E];
__device__ __align__(16) float g_k[OUT_E];
__device__ __align__(16) float g_v[OUT_E];
__device__ __align__(16) float g_ctx[OUT_E];
__device__ __align__(16) float g_attn[ATT_E];
__device__ float g_m[BHS];
__device__ float g_l[BHS];
__device__ float g_pm[(size_t)BATCH*NHEAD*NTILE*SEQ];
__device__ float g_pl[(size_t)BATCH*NHEAD*NTILE*SEQ];

static __device__ __forceinline__ uint32_t smem_u32(const void* p) {
    return (uint32_t)__cvta_generic_to_shared(p);
}

// fp32 -> (hi: truncated bf16, lo: bf16(x-hi)); 3-term product error ~2^-17.
static __device__ __forceinline__ void split_bf16(float x, __nv_bfloat16& hi, __nv_bfloat16& lo) {
    uint32_t u = __float_as_uint(x) & 0xFFFF0000u;
    hi = __ushort_as_bfloat16((unsigned short)(u >> 16));
    lo = __float2bfloat16(x - __uint_as_float(u));
}

// pack two fp32 into one bf16x2 register (hi parts / lo parts)
static __device__ __forceinline__ void split_pack2(float x, float y, uint32_t& h, uint32_t& l) {
    __nv_bfloat16 hx, lx, hy, ly;
    split_bf16(x, hx, lx);
    split_bf16(y, hy, ly);
    __nv_bfloat162 hh(hx, hy), ll(lx, ly);
    h = *(uint32_t*)&hh;
    l = *(uint32_t*)&ll;
}

#define MMA_BF16(Cr, Ar, B0, B1)                                               \
    asm volatile(                                                              \
        "mma.sync.aligned.m16n8k16.row.col.f32.bf16.bf16.f32 "                 \
        "{%0,%1,%2,%3},{%4,%5,%6,%7},{%8,%9},{%0,%1,%2,%3};"                   \
        : "+f"(Cr[0]), "+f"(Cr[1]), "+f"(Cr[2]), "+f"(Cr[3])                   \
        : "r"(Ar[0]), "r"(Ar[1]), "r"(Ar[2]), "r"(Ar[3]), "r"(B0), "r"(B1))

#define LDMATRIX_X4(R, addr)                                                   \
    asm volatile("ldmatrix.sync.aligned.m8n8.x4.shared.b16 {%0,%1,%2,%3}, [%4];" \
        : "=r"(R[0]), "=r"(R[1]), "=r"(R[2]), "=r"(R[3]) : "r"(addr))

#define LDMATRIX_X2(R, addr)                                                   \
    asm volatile("ldmatrix.sync.aligned.m8n8.x2.shared.b16 {%0,%1}, [%2];"     \
        : "=r"(R[0]), "=r"(R[1]) : "r"(addr))

#define LDMATRIX_X2_T(R, addr)                                                 \
    asm volatile("ldmatrix.sync.aligned.m8n8.x2.trans.shared.b16 {%0,%1}, [%2];" \
        : "=r"(R[0]), "=r"(R[1]) : "r"(addr))

#define LDMATRIX_X4_T(R0, R1, R2, R3, addr)                                    \
    asm volatile("ldmatrix.sync.aligned.m8n8.x4.trans.shared.b16 {%0,%1,%2,%3}, [%4];" \
        : "=r"(R0), "=r"(R1), "=r"(R2), "=r"(R3) : "r"(addr))

#define CP_ASYNC16(saddr, gptr)                                                \
    asm volatile("cp.async.cg.shared.global [%0], [%1], 16;"                   \
        :: "r"(saddr), "l"(gptr))
#define CP_COMMIT()  asm volatile("cp.async.commit_group;")
#define CP_WAIT(n)   asm volatile("cp.async.wait_group %0;" :: "n"(n))

static __device__ __forceinline__ void store_split4(__nv_bfloat16* dh, __nv_bfloat16* dl, float4 v) {
    __nv_bfloat16 h0,h1,h2,h3,l0,l1,l2,l3;
    split_bf16(v.x, h0, l0); split_bf16(v.y, h1, l1);
    split_bf16(v.z, h2, l2); split_bf16(v.w, h3, l3);
    ((__nv_bfloat162*)dh)[0] = __nv_bfloat162(h0, h1);
    ((__nv_bfloat162*)dh)[1] = __nv_bfloat162(h2, h3);
    ((__nv_bfloat162*)dl)[0] = __nv_bfloat162(l0, l1);
    ((__nv_bfloat162*)dl)[1] = __nv_bfloat162(l2, l3);
}

// ---------------------------------------------------------------------------
// Split-bf16 GEMM body with cp.async double-buffered staging (validated R16).
// ---------------------------------------------------------------------------
static __device__ __forceinline__
void gemm_body(const float* __restrict__ A, const float* __restrict__ W,
               const float* __restrict__ bias, float* __restrict__ C,
               char* smem_dyn, int bm, int bn)
{
    const int LDA = 40;
    const int LDB = 136;
    float* Araw = (float*)smem_dyn;                        // 2 x 128x32
    float* Wraw = Araw + 2 * 4096;                         // 2 x 32x128
    __nv_bfloat16* Ah = (__nv_bfloat16*)(Wraw + 2 * 4096); // 128*LDA
    __nv_bfloat16* Al = Ah + 128 * LDA;
    __nv_bfloat16* Bh = Al + 128 * LDA;                    // 32*LDB
    __nv_bfloat16* Bl = Bh + 32 * LDB;

    int tid  = threadIdx.x;
    int lane = tid & 31, warp = tid >> 5;
    int wm = (warp & 1) * 64, wn = (warp >> 1) * 32;

    int a_row[4], a_col[4], w_row[4], w_col[4];
#pragma unroll
    for (int i = 0; i < 4; i++) {
        int idx = tid + i * 256;
        a_row[i] = idx >> 3;  a_col[i] = (idx & 7) << 2;
        w_row[i] = idx >> 5;  w_col[i] = (idx & 31) << 2;
    }

#pragma unroll
    for (int i = 0; i < 4; i++) {
        CP_ASYNC16(smem_u32(&Araw[a_row[i] * 32 + a_col[i]]),
                   A + (size_t)(bm + a_row[i]) * D_MODEL + a_col[i]);
        CP_ASYNC16(smem_u32(&Wraw[w_row[i] * 128 + w_col[i]]),
                   W + (size_t)w_row[i] * D_MODEL + bn + w_col[i]);
    }
    CP_COMMIT();

    float c[4][4][4];
#pragma unroll
    for (int mt = 0; mt < 4; mt++)
#pragma unroll
        for (int nt = 0; nt < 4; nt++)
#pragma unroll
            for (int e = 0; e < 4; e++) c[mt][nt][e] = 0.f;

    for (int it = 0; it < 32; it++) {
        int buf  = it & 1;
        if (it + 1 < 32) {
            int nb = (it + 1) & 1;
            int k0 = (it + 1) * 32;
#pragma unroll
            for (int i = 0; i < 4; i++) {
                CP_ASYNC16(smem_u32(&Araw[nb * 4096 + a_row[i] * 32 + a_col[i]]),
                           A + (size_t)(bm + a_row[i]) * D_MODEL + k0 + a_col[i]);
                CP_ASYNC16(smem_u32(&Wraw[nb * 4096 + w_row[i] * 128 + w_col[i]]),
                           W + (size_t)(k0 + w_row[i]) * D_MODEL + bn + w_col[i]);
            }
            CP_COMMIT();
            CP_WAIT(1);
        } else {
            CP_WAIT(0);
        }
        __syncthreads();

#pragma unroll
        for (int i = 0; i < 4; i++) {
            float4 v = *(float4*)&Araw[buf * 4096 + a_row[i] * 32 + a_col[i]];
            store_split4(&Ah[a_row[i] * LDA + a_col[i]], &Al[a_row[i] * LDA + a_col[i]], v);
            float4 w = *(float4*)&Wraw[buf * 4096 + w_row[i] * 128 + w_col[i]];
            store_split4(&Bh[w_row[i] * LDB + w_col[i]], &Bl[w_row[i] * LDB + w_col[i]], w);
        }
        __syncthreads();

#pragma unroll
        for (int ks = 0; ks < 2; ks++) {
            int kb = ks * 16;
            uint32_t ah[4][4], al[4][4];
            {
                int grp = lane >> 3, r = lane & 7;
                int arow = wm + (grp & 1) * 8 + r;
                int acol = kb + ((grp & 2) ? 8 : 0);
#pragma unroll
                for (int mt = 0; mt < 4; mt++) {
                    LDMATRIX_X4(ah[mt], smem_u32(&Ah[(arow + mt * 16) * LDA + acol]));
                    LDMATRIX_X4(al[mt], smem_u32(&Al[(arow + mt * 16) * LDA + acol]));
                }
            }
            uint32_t bh[4][2], bl[4][2];
            {
                int brow = kb + ((lane >> 3) & 1) * 8 + (lane & 7);
#pragma unroll
                for (int nt = 0; nt < 4; nt++) {
                    int bcol = wn + nt * 8;
                    LDMATRIX_X2_T(bh[nt], smem_u32(&Bh[brow * LDB + bcol]));
                    LDMATRIX_X2_T(bl[nt], smem_u32(&Bl[brow * LDB + bcol]));
                }
            }
#pragma unroll
            for (int mt = 0; mt < 4; mt++)
#pragma unroll
                for (int nt = 0; nt < 4; nt++) {
                    MMA_BF16(c[mt][nt], ah[mt], bh[nt][0], bh[nt][1]);
                    MMA_BF16(c[mt][nt], ah[mt], bl[nt][0], bl[nt][1]);
                    MMA_BF16(c[mt][nt], al[mt], bh[nt][0], bh[nt][1]);
                }
        }
        __syncthreads();
    }

#pragma unroll
    for (int mt = 0; mt < 4; mt++)
#pragma unroll
        for (int nt = 0; nt < 4; nt++) {
            int row0 = bm + wm + mt * 16 + (lane >> 2);
            int col  = bn + wn + nt * 8 + (lane & 3) * 2;
            float b0 = bias[col], b1 = bias[col + 1];
            *(float2*)(C + (size_t)row0 * D_MODEL + col) =
                make_float2(c[mt][nt][0] + b0, c[mt][nt][1] + b1);
            *(float2*)(C + (size_t)(row0 + 8) * D_MODEL + col) =
                make_float2(c[mt][nt][2] + b0, c[mt][nt][3] + b1);
        }
}

// Merged QKV projection: blockIdx.z selects which of the three GEMMs.
__global__ __launch_bounds__(256, 2)
void gemm_qkv(const float* __restrict__ Q, const float* __restrict__ K,
              const float* __restrict__ V,
              const float* __restrict__ Wq, const float* __restrict__ Wk,
              const float* __restrict__ Wv,
              const float* __restrict__ bq, const float* __restrict__ bk,
              const float* __restrict__ bv,
              float* __restrict__ dq, float* __restrict__ dk, float* __restrict__ dv)
{
    extern __shared__ char smem_dyn[];
    int zz = blockIdx.z;
    const float* A    = (zz == 0) ? Q  : (zz == 1) ? K  : V;
    const float* W    = (zz == 0) ? Wq : (zz == 1) ? Wk : Wv;
    const float* bias = (zz == 0) ? bq : (zz == 1) ? bk : bv;
    float* C          = (zz == 0) ? dq : (zz == 1) ? dk : dv;
    gemm_body(A, W, bias, C, smem_dyn, blockIdx.y * 128, blockIdx.x * 128);
}

__global__ __launch_bounds__(256, 2)
void gemm_bias_mma(const float* __restrict__ A, const float* __restrict__ W,
                   const float* __restrict__ bias, float* __restrict__ C)
{
    extern __shared__ char smem_dyn[];
    gemm_body(A, W, bias, C, smem_dyn, blockIdx.y * 128, blockIdx.x * 128);
}

// ---------------------------------------------------------------------------
// Scores + fused partial softmax stats (validated R14).
// ---------------------------------------------------------------------------
__global__ __launch_bounds__(256, 2)
void scores_mma(const float* __restrict__ qg, const float* __restrict__ kg,
                float* __restrict__ attn)
{
    extern __shared__ __nv_bfloat16 sm_s[];
    const int LD = 72;
    __nv_bfloat16* Qh = sm_s;
    __nv_bfloat16* Ql = Qh + 128 * LD;
    __nv_bfloat16* Kh = Ql + 128 * LD;
    __nv_bfloat16* Kl = Kh + 128 * LD;
    float* red_m = (float*)(Kl + 128 * LD);   // [128][4]
    float* red_l = red_m + 128 * 4;           // [128][4]

    int tid = threadIdx.x, lane = tid & 31, warp = tid >> 5;
    int z = blockIdx.z, b = z >> 4, h = z & 15;
    int bm = blockIdx.y * 128, bn = blockIdx.x * 128;
    int wm = (warp & 1) * 64, wn = (warp >> 1) * 32;
    int nw = warp >> 1;

    const float* qb = qg + (size_t)b * SEQ * D_MODEL + h * DK;
    const float* kb = kg + (size_t)b * SEQ * D_MODEL + h * DK;

#pragma unroll
    for (int i = 0; i < 8; i++) {
        int idx = tid + i * 256;
        int row = idx >> 4, col = (idx & 15) << 2;
        float4 v = *(const float4*)(qb + (size_t)(bm + row) * D_MODEL + col);
        store_split4(&Qh[row * LD + col], &Ql[row * LD + col], v);
        float4 w = *(const float4*)(kb + (size_t)(bn + row) * D_MODEL + col);
        store_split4(&Kh[row * LD + col], &Kl[row * LD + col], w);
    }
    __syncthreads();

    float c[4][4][4];
#pragma unroll
    for (int mt = 0; mt < 4; mt++)
#pragma unroll
        for (int nt = 0; nt < 4; nt++)
#pragma unroll
            for (int e = 0; e < 4; e++) c[mt][nt][e] = 0.f;

#pragma unroll
    for (int ks = 0; ks < 4; ks++) {
        int kb16 = ks * 16;
        uint32_t ah[4][4], al[4][4];
        {
            int grp = lane >> 3, r = lane & 7;
            int arow = wm + (grp & 1) * 8 + r;
            int acol = kb16 + ((grp & 2) ? 8 : 0);
#pragma unroll
            for (int mt = 0; mt < 4; mt++) {
                LDMATRIX_X4(ah[mt], smem_u32(&Qh[(arow + mt * 16) * LD + acol]));
                LDMATRIX_X4(al[mt], smem_u32(&Ql[(arow + mt * 16) * LD + acol]));
            }
        }
        uint32_t bh[4][2], bl[4][2];
        {
            int nr = lane & 7;
            int bcol = kb16 + ((lane >> 3) & 1) * 8;
#pragma unroll
            for (int nt = 0; nt < 4; nt++) {
                int nrow = wn + nt * 8 + nr;
                LDMATRIX_X2(bh[nt], smem_u32(&Kh[nrow * LD + bcol]));
                LDMATRIX_X2(bl[nt], smem_u32(&Kl[nrow * LD + bcol]));
            }
        }
#pragma unroll
        for (int mt = 0; mt < 4; mt++)
#pragma unroll
            for (int nt = 0; nt < 4; nt++) {
                MMA_BF16(c[mt][nt], ah[mt], bh[nt][0], bh[nt][1]);
                MMA_BF16(c[mt][nt], ah[mt], bl[nt][0], bl[nt][1]);
                MMA_BF16(c[mt][nt], al[mt], bh[nt][0], bh[nt][1]);
            }
    }

    const float scale = 0.125f;
#pragma unroll
    for (int mt = 0; mt < 4; mt++)
#pragma unroll
        for (int nt = 0; nt < 4; nt++)
#pragma unroll
            for (int e = 0; e < 4; e++) c[mt][nt][e] *= scale;

    int rq = lane >> 2;
    bool qlead = (lane & 3) == 0;

#pragma unroll
    for (int mt = 0; mt < 4; mt++) {
        float m0 = -1e30f, m1 = -1e30f;
#pragma unroll
        for (int nt = 0; nt < 4; nt++) {
            m0 = fmaxf(m0, fmaxf(c[mt][nt][0], c[mt][nt][1]));
            m1 = fmaxf(m1, fmaxf(c[mt][nt][2], c[mt][nt][3]));
        }
        m0 = fmaxf(m0, __shfl_xor_sync(0xffffffffu, m0, 1));
        m0 = fmaxf(m0, __shfl_xor_sync(0xffffffffu, m0, 2));
        m1 = fmaxf(m1, __shfl_xor_sync(0xffffffffu, m1, 1));
        m1 = fmaxf(m1, __shfl_xor_sync(0xffffffffu, m1, 2));
        if (qlead) {
            red_m[(wm + mt * 16 + rq) * 4 + nw]     = m0;
            red_m[(wm + mt * 16 + 8 + rq) * 4 + nw] = m1;
        }
    }
    __syncthreads();

#pragma unroll
    for (int mt = 0; mt < 4; mt++) {
        int r0 = wm + mt * 16 + rq, r1 = r0 + 8;
        float M0 = fmaxf(fmaxf(red_m[r0*4+0], red_m[r0*4+1]), fmaxf(red_m[r0*4+2], red_m[r0*4+3]));
        float M1 = fmaxf(fmaxf(red_m[r1*4+0], red_m[r1*4+1]), fmaxf(red_m[r1*4+2], red_m[r1*4+3]));
        float s0 = 0.f, s1 = 0.f;
#pragma unroll
        for (int nt = 0; nt < 4; nt++) {
            s0 += __expf(c[mt][nt][0] - M0) + __expf(c[mt][nt][1] - M0);
            s1 += __expf(c[mt][nt][2] - M1) + __expf(c[mt][nt][3] - M1);
        }
        s0 += __shfl_xor_sync(0xffffffffu, s0, 1);
        s0 += __shfl_xor_sync(0xffffffffu, s0, 2);
        s1 += __shfl_xor_sync(0xffffffffu, s1, 1);
        s1 += __shfl_xor_sync(0xffffffffu, s1, 2);
        if (qlead) {
            red_l[r0 * 4 + nw] = s0;
            red_l[r1 * 4 + nw] = s1;
        }
    }
    __syncthreads();

    if (tid < 128) {
        int r = tid;
        float M = fmaxf(fmaxf(red_m[r*4+0], red_m[r*4+1]), fmaxf(red_m[r*4+2], red_m[r*4+3]));
        float L = red_l[r*4+0] + red_l[r*4+1] + red_l[r*4+2] + red_l[r*4+3];
        size_t off = ((size_t)z * NTILE + blockIdx.x) * SEQ + bm + r;
        g_pm[off] = M;
        g_pl[off] = L;
    }

    float* ab = attn + (size_t)z * SEQ * SEQ;
#pragma unroll
    for (int mt = 0; mt < 4; mt++)
#pragma unroll
        for (int nt = 0; nt < 4; nt++) {
            int row0 = bm + wm + mt * 16 + (lane >> 2);
            int col  = bn + wn + nt * 8 + (lane & 3) * 2;
            *(float2*)(ab + (size_t)row0 * SEQ + col) =
                make_float2(c[mt][nt][0], c[mt][nt][1]);
            *(float2*)(ab + (size_t)(row0 + 8) * SEQ + col) =
                make_float2(c[mt][nt][2], c[mt][nt][3]);
        }
}

// ---------------------------------------------------------------------------
__global__ __launch_bounds__(256)
void stats_combine(const float* __restrict__ pm, const float* __restrict__ pl)
{
    int R = blockIdx.x * 256 + threadIdx.x;
    int z = R >> 11, r = R & (SEQ - 1);
    size_t base = (size_t)z * NTILE * SEQ + r;

    float mv[NTILE];
    float M = -1e30f;
#pragma unroll
    for (int t = 0; t < NTILE; t++) {
        mv[t] = pm[base + (size_t)t * SEQ];
        M = fmaxf(M, mv[t]);
    }
    float L = 0.f;
#pragma unroll
    for (int t = 0; t < NTILE; t++)
        L += pl[base + (size_t)t * SEQ] * __expf(mv[t] - M);
    g_m[R] = M;
    g_l[R] = L;
}

// ---------------------------------------------------------------------------
// Context v2: 8 warps x 16 m-rows each, full 64 n-cols per warp.
// P is loaded from gmem DIRECTLY in A-fragment layout (rows lane>>2, +8;
// cols (lane&3)*2 +{0,1,8,9}), normalized (exp), written back (final attn),
// and split to bf16x2 in registers — no smem round trip for P.
// V chunk staged hi/lo in smem; B-fragments via x4-trans ldmatrix.
// ---------------------------------------------------------------------------
__global__ __launch_bounds__(256, 2)
void context_mma(float* __restrict__ attn, const float* __restrict__ vg,
                 float* __restrict__ ctx)
{
    extern __shared__ char sm_raw[];
    const int LD = 72;
    __nv_bfloat16* Vh = (__nv_bfloat16*)sm_raw;   // 64*LD
    __nv_bfloat16* Vl = Vh + 64 * LD;
    float* mrow  = (float*)(Vl + 64 * LD);        // 128
    float* rlrow = mrow + 128;

    int tid = threadIdx.x, lane = tid & 31, warp = tid >> 5;
    int z = blockIdx.y, b = z >> 4, h = z & 15;
    int bm = blockIdx.x * 128;
    int wm = warp * 16;

    if (tid < 128) {
        mrow[tid]  = g_m[(size_t)z * SEQ + bm + tid];
        rlrow[tid] = 1.0f / g_l[(size_t)z * SEQ + bm + tid];
    }
    __syncthreads();

    int lr0 = wm + (lane >> 2);       // local rows this thread owns
    int lr1 = lr0 + 8;
    float M0 = mrow[lr0], RL0 = rlrow[lr0];
    float M1 = mrow[lr1], RL1 = rlrow[lr1];

    float* ab = attn + (size_t)z * SEQ * SEQ;
    float* row0p = ab + (size_t)(bm + lr0) * SEQ + (lane & 3) * 2;
    float* row1p = ab + (size_t)(bm + lr1) * SEQ + (lane & 3) * 2;
    const float* vb = vg + (size_t)b * SEQ * D_MODEL + h * DK;

    float c[8][4];
#pragma unroll
    for (int nt = 0; nt < 8; nt++)
#pragma unroll
        for (int e = 0; e < 4; e++) c[nt][e] = 0.f;

    for (int k0 = 0; k0 < SEQ; k0 += 64) {
        // Stage V chunk 64x64 (split bf16): 1024 float4, 4 per thread.
#pragma unroll
        for (int i = 0; i < 4; i++) {
            int idx = tid + i * 256;
            int row = idx >> 4, col = (idx & 15) << 2;
            float4 v = *(const float4*)(vb + (size_t)(k0 + row) * D_MODEL + col);
            store_split4(&Vh[row * LD + col], &Vl[row * LD + col], v);
        }

        // Load this thread's P fragment elements (A-frag layout), all at once.
        float2 f0[4], f1[4], f2[4], f3[4];
#pragma unroll
        for (int ks = 0; ks < 4; ks++) {
            int cb = k0 + ks * 16;
            f0[ks] = *(float2*)(row0p + cb);       // (r0, k, k+1)
            f1[ks] = *(float2*)(row1p + cb);       // (r1, k, k+1)
            f2[ks] = *(float2*)(row0p + cb + 8);   // (r0, k+8, k+9)
            f3[ks] = *(float2*)(row1p + cb + 8);   // (r1, k+8, k+9)
        }
        // exp-normalize, write back final attention, split-pack to registers.
        uint32_t ah[4][4], al[4][4];
#pragma unroll
        for (int ks = 0; ks < 4; ks++) {
            int cb = k0 + ks * 16;
            f0[ks].x = __expf(f0[ks].x - M0) * RL0;
            f0[ks].y = __expf(f0[ks].y - M0) * RL0;
            f1[ks].x = __expf(f1[ks].x - M1) * RL1;
            f1[ks].y = __expf(f1[ks].y - M1) * RL1;
            f2[ks].x = __expf(f2[ks].x - M0) * RL0;
            f2[ks].y = __expf(f2[ks].y - M0) * RL0;
            f3[ks].x = __expf(f3[ks].x - M1) * RL1;
            f3[ks].y = __expf(f3[ks].y - M1) * RL1;
            *(float2*)(row0p + cb)     = f0[ks];
            *(float2*)(row1p + cb)     = f1[ks];
            *(float2*)(row0p + cb + 8) = f2[ks];
            *(float2*)(row1p + cb + 8) = f3[ks];
            split_pack2(f0[ks].x, f0[ks].y, ah[ks][0], al[ks][0]);
            split_pack2(f1[ks].x, f1[ks].y, ah[ks][1], al[ks][1]);
            split_pack2(f2[ks].x, f2[ks].y, ah[ks][2], al[ks][2]);
            split_pack2(f3[ks].x, f3[ks].y, ah[ks][3], al[ks][3]);
        }
        __syncthreads();   // V staged (and prev iter's V fully consumed)

#pragma unroll
        for (int ks = 0; ks < 4; ks++) {
            // B-fragments for all 8 n-tiles via x4-trans (2 n-tiles per ld).
            uint32_t bh[8][2], bl[8][2];
            int vrow = ks * 16 + ((lane >> 3) & 1) * 8 + (lane & 7);
            int vcol8 = ((lane >> 4) & 1) * 8;
#pragma unroll
            for (int np = 0; np < 4; np++) {
                LDMATRIX_X4_T(bh[np*2][0], bh[np*2][1], bh[np*2+1][0], bh[np*2+1][1],
                              smem_u32(&Vh[vrow * LD + np * 16 + vcol8]));
                LDMATRIX_X4_T(bl[np*2][0], bl[np*2][1], bl[np*2+1][0], bl[np*2+1][1],
                              smem_u32(&Vl[vrow * LD + np * 16 + vcol8]));
            }
#pragma unroll
            for (int nt = 0; nt < 8; nt++) {
                MMA_BF16(c[nt], ah[ks], bh[nt][0], bh[nt][1]);
                MMA_BF16(c[nt], ah[ks], bl[nt][0], bl[nt][1]);
                MMA_BF16(c[nt], al[ks], bh[nt][0], bh[nt][1]);
            }
        }
        __syncthreads();   // V consumed; safe to restage next chunk
    }

#pragma unroll
    for (int nt = 0; nt < 8; nt++) {
        int col = h * DK + nt * 8 + (lane & 3) * 2;
        *(float2*)(ctx + (size_t)(b * SEQ + bm + lr0) * D_MODEL + col) =
            make_float2(c[nt][0], c[nt][1]);
        *(float2*)(ctx + (size_t)(b * SEQ + bm + lr1) * D_MODEL + col) =
            make_float2(c[nt][2], c[nt][3]);
    }
}

// ---------------------------------------------------------------------------
extern "C" void kernel_launch(void* const* d_in, const int* in_sizes, int n_in,
                              void* d_out, int out_size)
{
    const float* Q   = (const float*)d_in[0];
    const float* K   = (const float*)d_in[1];
    const float* V   = (const float*)d_in[2];
    const float* Wq  = (const float*)d_in[3];
    const float* bq  = (const float*)d_in[4];
    const float* Wk  = (const float*)d_in[5];
    const float* bk  = (const float*)d_in[6];
    const float* Wv  = (const float*)d_in[7];
    const float* bv  = (const float*)d_in[8];
    const float* Wfc = (const float*)d_in[9];
    const float* bfc = (const float*)d_in[10];

    float* out = (float*)d_out;

    void *pq, *pk, *pv, *pc, *pa, *ppm, *ppl;
    cudaGetSymbolAddress(&pq, g_q);
    cudaGetSymbolAddress(&pk, g_k);
    cudaGetSymbolAddress(&pv, g_v);
    cudaGetSymbolAddress(&pc, g_ctx);
    cudaGetSymbolAddress(&pa, g_attn);
    cudaGetSymbolAddress(&ppm, g_pm);
    cudaGetSymbolAddress(&ppl, g_pl);
    float* dq   = (float*)pq;
    float* dk   = (float*)pk;
    float* dv   = (float*)pv;
    float* dctx = (float*)pc;

    float* attn = ((size_t)out_size >= OUT_E + ATT_E) ? (out + OUT_E)
                                                      : (float*)pa;

    const int GEMM_SMEM = (2*4096 + 2*4096) * 4 + (2*128*40 + 2*32*136) * 2; // 103,424 B
    const int SC_SMEM   = 4 * 128 * 72 * 2 + 2 * 128 * 4 * 4;                // 77,824 B
    const int CTX_SMEM  = 2 * 64 * 72 * 2 + 2 * 128 * 4;                     // 19,456 B
    cudaFuncSetAttribute(gemm_qkv, cudaFuncAttributeMaxDynamicSharedMemorySize, GEMM_SMEM);
    cudaFuncSetAttribute(gemm_bias_mma, cudaFuncAttributeMaxDynamicSharedMemorySize, GEMM_SMEM);
    cudaFuncSetAttribute(scores_mma, cudaFuncAttributeMaxDynamicSharedMemorySize, SC_SMEM);
    cudaFuncSetAttribute(context_mma, cudaFuncAttributeMaxDynamicSharedMemorySize, CTX_SMEM);

    dim3 qkv_grid(D_MODEL / 128, M_TOT / 128, 3);      // (8, 32, 3)
    gemm_qkv<<<qkv_grid, 256, GEMM_SMEM>>>(Q, K, V, Wq, Wk, Wv, bq, bk, bv, dq, dk, dv);

    dim3 sc_grid(SEQ / 128, SEQ / 128, BATCH * NHEAD); // (16, 16, 32)
    scores_mma<<<sc_grid, 256, SC_SMEM>>>(dq, dk, attn);

    stats_combine<<<BHS / 256, 256>>>((const float*)ppm, (const float*)ppl);

    dim3 ctx_grid(SEQ / 128, BATCH * NHEAD);           // (16, 32)
    context_mma<<<ctx_grid, 256, CTX_SMEM>>>(attn, dv, dctx);

    dim3 gemm_grid(D_MODEL / 128, M_TOT / 128);        // (8, 32)
    gemm_bias_mma<<<gemm_grid, 256, GEMM_SMEM>>>(dctx, Wfc, bfc, out);
}